// round 2
// baseline (speedup 1.0000x reference)
#include <cuda_runtime.h>

#define Bsz 4096
#define Isz 256
#define Osz 256
#define Gsz 32
#define SLOTS 65          // 32 cos + 32 sin + 1 silu-base feature slots per i
#define BT 128            // B tile
#define OT 64             // O tile
#define GEMM_SMEM (SLOTS*BT*4 + SLOTS*OT*8)

// scratch (allocation-free rule: __device__ globals)
__device__ float g_c1[Isz * Bsz];      // cos(x)  transposed [i][b]
__device__ float g_s1[Isz * Bsz];      // sin(x)  transposed [i][b]
__device__ float g_base[Isz * Bsz];    // silu(x) transposed [i][b]
__device__ float g_W[Isz * SLOTS * Osz]; // folded weights [i][slot][j]

__device__ __forceinline__ unsigned long long ffma2(unsigned long long a,
                                                    unsigned long long b,
                                                    unsigned long long c) {
    unsigned long long d;
    asm("fma.rn.f32x2 %0, %1, %2, %3;" : "=l"(d) : "l"(a), "l"(b), "l"(c));
    return d;
}

// Kernel 1: per-(b,i) transcendentals, written i-major for coalesced GEMM loads
__global__ void kan_xform(const float* __restrict__ x) {
    int i = blockIdx.y;
    int b = blockIdx.x * blockDim.x + threadIdx.x;
    float v = x[(size_t)b * Isz + i];
    float s, c;
    __sincosf(v, &s, &c);
    g_c1[i * Bsz + b] = c;
    g_s1[i * Bsz + b] = s;
    g_base[i * Bsz + b] = v * (1.0f / (1.0f + __expf(-v)));
}

// Kernel 2: fold mask/scale_fft/scale_base into fouriercoeffs -> W[i][slot][j]
__global__ void kan_prep(const float* __restrict__ fc, const float* __restrict__ mask,
                         const float* __restrict__ sb, const float* __restrict__ sf) {
    int i = blockIdx.x;   // input dim
    int j = threadIdx.x;  // output dim
    float m  = mask[i * Osz + j];
    float wf = sf[i * Osz + j] * m;
    float wb = sb[i * Osz + j] * m;
    const float* f0 = fc + ((size_t)j * Isz + i) * Gsz;            // fc[0][j][i][:]
    const float* f1 = f0 + (size_t)Osz * Isz * Gsz;                // fc[1][j][i][:]
    float* wr = g_W + (size_t)i * SLOTS * Osz;
#pragma unroll
    for (int k = 0; k < Gsz; ++k) {
        wr[k * Osz + j]         = wf * f0[k];   // cos weights
        wr[(Gsz + k) * Osz + j] = wf * f1[k];   // sin weights
    }
    wr[64 * Osz + j] = wb;                      // silu-base weight
}

// Kernel 3: fused feature-generating GEMM, f32x2 packed over b-pairs.
// 256 threads, tile 128b x 64o, thread tile 8b(4 f32x2 pairs) x 4o (strided by 16).
__global__ void __launch_bounds__(256, 1)
kan_gemm(const float* __restrict__ bias, float* __restrict__ out) {
    extern __shared__ float smem[];
    float*  sA = smem;                          // [SLOTS][BT] features
    float2* sW = (float2*)(smem + SLOTS * BT);  // [SLOTS][OT] duplicated (w,w)

    const int b0  = blockIdx.x * BT;
    const int o0  = blockIdx.y * OT;
    const int tid = threadIdx.x;
    const int to  = tid & 15;   // 16 o-groups (strided o: to, to+16, to+32, to+48)
    const int tb  = tid >> 4;   // 16 b-groups of 8 rows

    unsigned long long acc[4][4];
#pragma unroll
    for (int p = 0; p < 4; ++p)
#pragma unroll
        for (int q = 0; q < 4; ++q) acc[p][q] = 0ull;

    for (int i = 0; i < Isz; ++i) {
        __syncthreads();
        if (tid < BT) {
            // warps 0-3: angle-addition recurrence -> 65 feature rows
            int b = tid;
            float c1 = g_c1[i * Bsz + b0 + b];
            float s1 = g_s1[i * Bsz + b0 + b];
            sA[0 * BT + b]  = c1;
            sA[32 * BT + b] = s1;
            sA[64 * BT + b] = g_base[i * Bsz + b0 + b];
            float c = c1, s = s1;
#pragma unroll
            for (int k = 1; k < 32; ++k) {
                float cn = fmaf(c, c1, -(s * s1));   // cos((k+1)x)
                float sn = fmaf(s, c1,   c * s1);    // sin((k+1)x)
                c = cn; s = sn;
                sA[k * BT + b]        = c;
                sA[(32 + k) * BT + b] = s;
            }
        } else {
            // warps 4-7: stage weights (duplicated into f32x2 lanes)
            int t = tid - BT;
            const float4* src = (const float4*)(g_W + (size_t)i * SLOTS * Osz + o0);
#pragma unroll
            for (int it = 0; it < 9; ++it) {
                int idx = t + it * 128;
                if (idx < SLOTS * 16) {
                    int slot = idx >> 4;
                    int f4   = idx & 15;
                    float4 w = src[slot * (Osz / 4) + f4];
                    float2* dst = sW + slot * OT + f4 * 4;
                    dst[0] = make_float2(w.x, w.x);
                    dst[1] = make_float2(w.y, w.y);
                    dst[2] = make_float2(w.z, w.z);
                    dst[3] = make_float2(w.w, w.w);
                }
            }
        }
        __syncthreads();

        // MAC over the 65 feature slots of this i
#pragma unroll 13
        for (int s = 0; s < SLOTS; ++s) {
            const ulonglong2* ap = (const ulonglong2*)(sA + s * BT + tb * 8);
            ulonglong2 A01 = ap[0];              // b pairs {0,1},{2,3}
            ulonglong2 A23 = ap[1];              // b pairs {4,5},{6,7}
            const float2* wrow = sW + s * OT;
#pragma unroll
            for (int q = 0; q < 4; ++q) {
                unsigned long long w =
                    *(const unsigned long long*)(wrow + to + 16 * q);
                acc[0][q] = ffma2(A01.x, w, acc[0][q]);
                acc[1][q] = ffma2(A01.y, w, acc[1][q]);
                acc[2][q] = ffma2(A23.x, w, acc[2][q]);
                acc[3][q] = ffma2(A23.y, w, acc[3][q]);
            }
        }
    }

    // epilogue: unpack b-pairs, add bias
#pragma unroll
    for (int q = 0; q < 4; ++q) {
        int o = o0 + to + 16 * q;
        float bv = bias[o];
#pragma unroll
        for (int p = 0; p < 4; ++p) {
            float2 v = *reinterpret_cast<float2*>(&acc[p][q]);
            int br = b0 + tb * 8 + 2 * p;
            out[(size_t)br * Osz + o]       = v.x + bv;
            out[(size_t)(br + 1) * Osz + o] = v.y + bv;
        }
    }
}

extern "C" void kernel_launch(void* const* d_in, const int* in_sizes, int n_in,
                              void* d_out, int out_size) {
    const float* x    = (const float*)d_in[0];
    const float* fc   = (const float*)d_in[1];
    const float* bias = (const float*)d_in[2];
    const float* mask = (const float*)d_in[3];
    const float* sb   = (const float*)d_in[4];
    const float* sf   = (const float*)d_in[5];
    float* out = (float*)d_out;

    cudaFuncSetAttribute(kan_gemm, cudaFuncAttributeMaxDynamicSharedMemorySize,
                         GEMM_SMEM);

    kan_xform<<<dim3(Bsz / 256, Isz), 256>>>(x);
    kan_prep<<<Isz, Osz>>>(fc, mask, sb, sf);
    kan_gemm<<<dim3(Bsz / BT, Osz / OT), 256, GEMM_SMEM>>>(bias, out);
}

// round 4
// speedup vs baseline: 2.1591x; 2.1591x over previous
#include <cuda_runtime.h>
#include <cuda_bf16.h>
#include <cstdint>

#define Bq 4096
#define Iq 256
#define Oq 256
#define NCH 260                 // 256 fourier chunks + 4 base chunks (K=64 each)
// stage layout: Ah 16K | Al 16K | Wh 8K | Wl 8K
#define AHo 0
#define ALo 16384
#define WHo 32768
#define WLo 40960
#define STG 49152
#define GSMEM (2*STG + 1024)

// ---------- scratch (__device__ globals only) ----------
__device__ float g_c1[(size_t)Iq * Bq];
__device__ float g_s1[(size_t)Iq * Bq];
__device__ float g_c17[(size_t)Iq * Bq];
__device__ float g_s17[(size_t)Iq * Bq];
__device__ __align__(16) unsigned short g_bh[(size_t)Bq * Iq];       // silu hi [b][i]
__device__ __align__(16) unsigned short g_bl[(size_t)Bq * Iq];       // silu lo [b][i]
__device__ __align__(16) unsigned short g_Wh[(size_t)NCH * Oq * 64]; // [chunk][j][slot]
__device__ __align__(16) unsigned short g_Wl[(size_t)NCH * Oq * 64];

// ---------- helpers ----------
__device__ __forceinline__ uint32_t smem_u32(const void* p) {
    uint32_t a;
    asm("{ .reg .u64 t; cvta.to.shared.u64 t, %1; cvt.u32.u64 %0, t; }" : "=r"(a) : "l"(p));
    return a;
}
__device__ __forceinline__ uint32_t swz(uint32_t off) { return off ^ ((off >> 3) & 0x70); }
__device__ __forceinline__ uint32_t hipack(float a, float b) {  // trunc-bf16 pair, a->low
    uint32_t r;
    asm("prmt.b32 %0, %1, %2, 0x7632;" : "=r"(r) : "r"(__float_as_uint(a)), "r"(__float_as_uint(b)));
    return r;
}
__device__ __forceinline__ float losub(float v) {
    return v - __uint_as_float(__float_as_uint(v) & 0xFFFF0000u);
}
__device__ __forceinline__ uint32_t lopack(float a, float b) {  // rn-bf16 pair, a->low
    uint32_t r;
    asm("cvt.rn.bf16x2.f32 %0, %1, %2;" : "=r"(r) : "f"(b), "f"(a));
    return r;
}
__device__ __forceinline__ void rot(float& c, float& s, float c1, float s1) {
    float t = fmaf(c, c1, -(s * s1));
    float u = fmaf(s, c1, c * s1);
    c = t; s = u;
}
__device__ __forceinline__ unsigned short f2bfu(float f) {
    __nv_bfloat16 b = __float2bfloat16(f);
    return *reinterpret_cast<unsigned short*>(&b);
}

#define STS128(a, v) asm volatile("st.shared.v4.b32 [%0], {%1,%2,%3,%4};" \
    :: "r"(a), "r"((v).x), "r"((v).y), "r"((v).z), "r"((v).w) : "memory")
#define LDSM4(r, addr) asm volatile( \
    "ldmatrix.sync.aligned.m8n8.x4.shared.b16 {%0,%1,%2,%3}, [%4];" \
    : "=r"((r)[0]), "=r"((r)[1]), "=r"((r)[2]), "=r"((r)[3]) : "r"(addr))
#define HMMA(d, a, b0v, b1v) asm volatile( \
    "mma.sync.aligned.m16n8k16.row.col.f32.bf16.bf16.f32 " \
    "{%0,%1,%2,%3}, {%4,%5,%6,%7}, {%8,%9}, {%0,%1,%2,%3};" \
    : "+f"((d)[0]), "+f"((d)[1]), "+f"((d)[2]), "+f"((d)[3]) \
    : "r"((a)[0]), "r"((a)[1]), "r"((a)[2]), "r"((a)[3]), "r"(b0v), "r"(b1v))

// ---------- kernel 1: sincos/silu transform ----------
__global__ void kan_xform(const float* __restrict__ x) {
    __shared__ float tx[32][33];
    int b0 = blockIdx.x * 32, i0 = blockIdx.y * 32;
    int tid = threadIdx.x;
#pragma unroll
    for (int it = 0; it < 4; ++it) {
        int idx = tid + it * 256;
        int bb = idx >> 5, ii = idx & 31;
        float v = x[(size_t)(b0 + bb) * Iq + i0 + ii];
        tx[bb][ii] = v;
        float sl = v / (1.0f + expf(-v));
        uint32_t hb = __float_as_uint(sl) & 0xFFFF0000u;
        size_t o = (size_t)(b0 + bb) * Iq + i0 + ii;
        g_bh[o] = (unsigned short)(hb >> 16);
        g_bl[o] = f2bfu(sl - __uint_as_float(hb));
    }
    __syncthreads();
#pragma unroll
    for (int it = 0; it < 4; ++it) {
        int idx = tid + it * 256;
        int ii = idx >> 5, bb = idx & 31;
        float v = tx[bb][ii];
        float s, c;
        sincosf(v, &s, &c);
        size_t o = (size_t)(i0 + ii) * Bq + b0 + bb;
        g_c1[o] = c; g_s1[o] = s;
        sincosf(17.0f * v, &s, &c);
        g_c17[o] = c; g_s17[o] = s;
    }
}

// ---------- kernel 2: fold + bf16-split weights ----------
__global__ void kan_prep(const float* __restrict__ fc, const float* __restrict__ mask,
                         const float* __restrict__ sb, const float* __restrict__ sf) {
    int blk = blockIdx.x, j = threadIdx.x;
    unsigned short* dh = g_Wh + ((size_t)blk * Oq + j) * 64;
    unsigned short* dl = g_Wl + ((size_t)blk * Oq + j) * 64;
    if (blk < Iq) {
        int i = blk;
        float m = mask[i * Oq + j];
        float wf = sf[i * Oq + j] * m;
        const float* f0 = fc + ((size_t)j * Iq + i) * 32;
        const float* f1 = f0 + (size_t)Oq * Iq * 32;
        for (int g = 0; g < 8; ++g) {
            uint4 vh, vl;
            uint32_t* ph = &vh.x; uint32_t* pl = &vl.x;
            for (int e = 0; e < 4; ++e) {
                int s0 = g * 8 + 2 * e;
                float w0 = (s0 < 32) ? wf * f0[s0] : wf * f1[s0 - 32];
                float w1 = (s0 + 1 < 32) ? wf * f0[s0 + 1] : wf * f1[s0 - 31];
                ph[e] = hipack(w0, w1);
                pl[e] = lopack(losub(w0), losub(w1));
            }
            *reinterpret_cast<uint4*>(dh + g * 8) = vh;
            *reinterpret_cast<uint4*>(dl + g * 8) = vl;
        }
    } else {
        int cb = blk - Iq;
        for (int g = 0; g < 8; ++g) {
            uint4 vh, vl;
            uint32_t* ph = &vh.x; uint32_t* pl = &vl.x;
            for (int e = 0; e < 4; ++e) {
                int s0 = g * 8 + 2 * e;
                int ia = cb * 64 + s0, ib = ia + 1;
                float w0 = mask[ia * Oq + j] * sb[ia * Oq + j];
                float w1 = mask[ib * Oq + j] * sb[ib * Oq + j];
                ph[e] = hipack(w0, w1);
                pl[e] = lopack(losub(w0), losub(w1));
            }
            *reinterpret_cast<uint4*>(dh + g * 8) = vh;
            *reinterpret_cast<uint4*>(dl + g * 8) = vl;
        }
    }
}

// ---------- kernel 3: HMMA fused GEMM ----------
__global__ void __launch_bounds__(256, 1)
kan_gemm(const float* __restrict__ bias, float* __restrict__ out) {
    extern __shared__ char smem[];
    const uint32_t sbase = (smem_u32(smem) + 127) & ~127u;

    const int tid = threadIdx.x, lane = tid & 31, wid = tid >> 5;
    const int wm = wid & 3, wn = wid >> 2;          // warp grid 4m x 2n
    const int b0 = blockIdx.x * 128, o0 = blockIdx.y * 64;

    const int gm = tid >> 1, gh = tid & 1;          // A-gen: row, half
    const int wrow = tid >> 2, wq = tid & 3;        // W-load: n-row, quarter

    float acc[2][4][4];
#pragma unroll
    for (int mt = 0; mt < 2; ++mt)
#pragma unroll
        for (int nf = 0; nf < 4; ++nf)
#pragma unroll
            for (int e = 0; e < 4; ++e) acc[mt][nf][e] = 0.0f;

    uint32_t aH[16], aL[16];
    uint4 wR[4];
    float sd_c1, sd_s1, sd_cc, sd_ss;

    // --- prologue: seeds + W for chunk 0, generate A(0) ---
    {
        size_t gb = (size_t)0 * Bq + b0 + gm;
        sd_c1 = g_c1[gb]; sd_s1 = g_s1[gb];
        if (gh) { sd_cc = g_c17[gb]; sd_ss = g_s17[gb]; }
        else    { sd_cc = sd_c1;     sd_ss = sd_s1; }
        const uint4* ph = (const uint4*)(g_Wh + ((size_t)0 * Oq + o0 + wrow) * 64 + wq * 16);
        const uint4* pl = (const uint4*)(g_Wl + ((size_t)0 * Oq + o0 + wrow) * 64 + wq * 16);
        wR[0] = ph[0]; wR[1] = ph[1]; wR[2] = pl[0]; wR[3] = pl[1];
        float cc = sd_cc, ss = sd_ss;
#pragma unroll
        for (int p = 0; p < 8; ++p) {
            float ca = cc, sa = ss; rot(cc, ss, sd_c1, sd_s1);
            float cb = cc, sb2 = ss; rot(cc, ss, sd_c1, sd_s1);
            aH[p] = hipack(ca, cb);  aL[p] = lopack(losub(ca), losub(cb));
            aH[8 + p] = hipack(sa, sb2); aL[8 + p] = lopack(losub(sa), losub(sb2));
        }
    }

    const uint32_t arow = (uint32_t)gm * 128;
    const uint32_t wroff = (uint32_t)wrow * 128 + wq * 32;
    const uint32_t aoff = (uint32_t)(wm * 32 + (lane & 15)) * 128 + (lane >> 4) * 16;
    const uint32_t boff = (uint32_t)(wn * 32 + (lane & 7) + ((lane >> 4) << 3)) * 128
                        + ((lane >> 3) & 1) * 16;

    for (int c = 0; c < NCH; ++c) {
        const uint32_t st = sbase + (c & 1) * STG;

        __syncthreads();   // stage (c&1) free (consumers of c-2 done)

        // ---- STS A ----
        {
            uint32_t col = gh * 32;
            STS128(st + AHo + swz(arow + col),       make_uint4(aH[0], aH[1], aH[2], aH[3]));
            STS128(st + AHo + swz(arow + col + 16),  make_uint4(aH[4], aH[5], aH[6], aH[7]));
            STS128(st + AHo + swz(arow + 64 + col),      make_uint4(aH[8], aH[9], aH[10], aH[11]));
            STS128(st + AHo + swz(arow + 64 + col + 16), make_uint4(aH[12], aH[13], aH[14], aH[15]));
            STS128(st + ALo + swz(arow + col),       make_uint4(aL[0], aL[1], aL[2], aL[3]));
            STS128(st + ALo + swz(arow + col + 16),  make_uint4(aL[4], aL[5], aL[6], aL[7]));
            STS128(st + ALo + swz(arow + 64 + col),      make_uint4(aL[8], aL[9], aL[10], aL[11]));
            STS128(st + ALo + swz(arow + 64 + col + 16), make_uint4(aL[12], aL[13], aL[14], aL[15]));
        }
        // ---- STS W ----
        STS128(st + WHo + swz(wroff),      wR[0]);
        STS128(st + WHo + swz(wroff + 16), wR[1]);
        STS128(st + WLo + swz(wroff),      wR[2]);
        STS128(st + WLo + swz(wroff + 16), wR[3]);

        __syncthreads();   // stage (c&1) full

        // ---- prefetch chunk c+1 (loads first: latency hidden under MMA) ----
        const int cn = c + 1;
        if (cn < NCH) {
            const uint4* ph = (const uint4*)(g_Wh + ((size_t)cn * Oq + o0 + wrow) * 64 + wq * 16);
            const uint4* pl = (const uint4*)(g_Wl + ((size_t)cn * Oq + o0 + wrow) * 64 + wq * 16);
            wR[0] = ph[0]; wR[1] = ph[1]; wR[2] = pl[0]; wR[3] = pl[1];
            if (cn < Iq) {
                size_t gb = (size_t)cn * Bq + b0 + gm;
                sd_c1 = g_c1[gb]; sd_s1 = g_s1[gb];
                if (gh) { sd_cc = g_c17[gb]; sd_ss = g_s17[gb]; }
                else    { sd_cc = sd_c1;     sd_ss = sd_s1; }
            }
        }

        // ---- MMA on chunk c ----
#pragma unroll
        for (int kk = 0; kk < 4; ++kk) {
            uint32_t ah0[4], ah1[4], al0[4], al1[4], wh0[4], wh1[4], wl0[4], wl1[4];
            LDSM4(ah0, st + AHo + swz(aoff + kk * 32));
            LDSM4(ah1, st + AHo + swz(aoff + 2048 + kk * 32));
            LDSM4(al0, st + ALo + swz(aoff + kk * 32));
            LDSM4(al1, st + ALo + swz(aoff + 2048 + kk * 32));
            LDSM4(wh0, st + WHo + swz(boff + kk * 32));
            LDSM4(wh1, st + WHo + swz(boff + 2048 + kk * 32));
            LDSM4(wl0, st + WLo + swz(boff + kk * 32));
            LDSM4(wl1, st + WLo + swz(boff + 2048 + kk * 32));
#pragma unroll
            for (int mt = 0; mt < 2; ++mt) {
                const uint32_t* A  = mt ? ah1 : ah0;
                const uint32_t* Al = mt ? al1 : al0;
                HMMA(acc[mt][0], A,  wh0[0], wh0[1]);
                HMMA(acc[mt][0], Al, wh0[0], wh0[1]);
                HMMA(acc[mt][0], A,  wl0[0], wl0[1]);
                HMMA(acc[mt][1], A,  wh0[2], wh0[3]);
                HMMA(acc[mt][1], Al, wh0[2], wh0[3]);
                HMMA(acc[mt][1], A,  wl0[2], wl0[3]);
                HMMA(acc[mt][2], A,  wh1[0], wh1[1]);
                HMMA(acc[mt][2], Al, wh1[0], wh1[1]);
                HMMA(acc[mt][2], A,  wl1[0], wl1[1]);
                HMMA(acc[mt][3], A,  wh1[2], wh1[3]);
                HMMA(acc[mt][3], Al, wh1[2], wh1[3]);
                HMMA(acc[mt][3], A,  wl1[2], wl1[3]);
            }
        }

        // ---- generate A(c+1) ----
        if (cn < NCH) {
            if (cn < Iq) {
                float cc = sd_cc, ss = sd_ss;
#pragma unroll
                for (int p = 0; p < 8; ++p) {
                    float ca = cc, sa = ss; rot(cc, ss, sd_c1, sd_s1);
                    float cb = cc, sb2 = ss; rot(cc, ss, sd_c1, sd_s1);
                    aH[p] = hipack(ca, cb);  aL[p] = lopack(losub(ca), losub(cb));
                    aH[8 + p] = hipack(sa, sb2); aL[8 + p] = lopack(losub(sa), losub(sb2));
                }
            } else {
                int cb = cn - Iq;
                const unsigned short* ph = g_bh + (size_t)(b0 + gm) * Iq + cb * 64;
                const unsigned short* pl = g_bl + (size_t)(b0 + gm) * Iq + cb * 64;
                uint4 v;
                v = *(const uint4*)(ph + 16 * gh);      aH[0]=v.x; aH[1]=v.y; aH[2]=v.z; aH[3]=v.w;
                v = *(const uint4*)(ph + 16 * gh + 8);  aH[4]=v.x; aH[5]=v.y; aH[6]=v.z; aH[7]=v.w;
                v = *(const uint4*)(ph + 32 + 16 * gh);     aH[8]=v.x; aH[9]=v.y; aH[10]=v.z; aH[11]=v.w;
                v = *(const uint4*)(ph + 32 + 16 * gh + 8); aH[12]=v.x; aH[13]=v.y; aH[14]=v.z; aH[15]=v.w;
                v = *(const uint4*)(pl + 16 * gh);      aL[0]=v.x; aL[1]=v.y; aL[2]=v.z; aL[3]=v.w;
                v = *(const uint4*)(pl + 16 * gh + 8);  aL[4]=v.x; aL[5]=v.y; aL[6]=v.z; aL[7]=v.w;
                v = *(const uint4*)(pl + 32 + 16 * gh);     aL[8]=v.x; aL[9]=v.y; aL[10]=v.z; aL[11]=v.w;
                v = *(const uint4*)(pl + 32 + 16 * gh + 8); aL[12]=v.x; aL[13]=v.y; aL[14]=v.z; aL[15]=v.w;
            }
        }
    }

    // ---- epilogue ----
#pragma unroll
    for (int mt = 0; mt < 2; ++mt) {
#pragma unroll
        for (int nf = 0; nf < 4; ++nf) {
            int row = b0 + wm * 32 + mt * 16 + (lane >> 2);
            int col = o0 + wn * 32 + nf * 8 + 2 * (lane & 3);
            float bv0 = bias[col], bv1 = bias[col + 1];
            float2 v0 = make_float2(acc[mt][nf][0] + bv0, acc[mt][nf][1] + bv1);
            float2 v1 = make_float2(acc[mt][nf][2] + bv0, acc[mt][nf][3] + bv1);
            *reinterpret_cast<float2*>(out + (size_t)row * Oq + col) = v0;
            *reinterpret_cast<float2*>(out + (size_t)(row + 8) * Oq + col) = v1;
        }
    }
}

extern "C" void kernel_launch(void* const* d_in, const int* in_sizes, int n_in,
                              void* d_out, int out_size) {
    const float* x    = (const float*)d_in[0];
    const float* fc   = (const float*)d_in[1];
    const float* bias = (const float*)d_in[2];
    const float* mask = (const float*)d_in[3];
    const float* sb   = (const float*)d_in[4];
    const float* sf   = (const float*)d_in[5];
    float* out = (float*)d_out;

    cudaFuncSetAttribute(kan_gemm, cudaFuncAttributeMaxDynamicSharedMemorySize, GSMEM);

    kan_xform<<<dim3(Bq / 32, Iq / 32), 256>>>(x);
    kan_prep<<<NCH, Oq>>>(fc, mask, sb, sf);
    kan_gemm<<<dim3(Bq / 128, Oq / 64), 256, GSMEM>>>(bias, out);
}

// round 5
// speedup vs baseline: 2.9854x; 1.3827x over previous
#include <cuda_runtime.h>
#include <cuda_fp16.h>
#include <cstdint>

#define Bq 4096
#define Iq 256
#define Oq 256
#define NCH 260                 // 256 fourier chunks + 4 base chunks (K=64 each)
// stage layout: A 16K | Wh 8K | Wl 8K
#define AHo 0
#define WHo 16384
#define WLo 24576
#define STG 32768
#define GSMEM (2*STG + 1024)

// ---------- scratch (__device__ globals only) ----------
__device__ float g_c1[(size_t)Iq * Bq];
__device__ float g_s1[(size_t)Iq * Bq];
__device__ float g_c17[(size_t)Iq * Bq];
__device__ float g_s17[(size_t)Iq * Bq];
__device__ __align__(16) unsigned short g_bh[(size_t)Bq * Iq];       // silu fp16 [b][i]
__device__ __align__(16) unsigned short g_Wh[(size_t)NCH * Oq * 64]; // fp16 hi [chunk][j][slot]
__device__ __align__(16) unsigned short g_Wl[(size_t)NCH * Oq * 64]; // fp16 lo residual

// ---------- helpers ----------
__device__ __forceinline__ uint32_t smem_u32(const void* p) {
    uint32_t a;
    asm("{ .reg .u64 t; cvta.to.shared.u64 t, %1; cvt.u32.u64 %0, t; }" : "=r"(a) : "l"(p));
    return a;
}
__device__ __forceinline__ uint32_t swz(uint32_t off) { return off ^ ((off >> 3) & 0x70); }
__device__ __forceinline__ uint32_t h2pack(float a, float b) {  // a->low half
    uint32_t r;
    asm("cvt.rn.f16x2.f32 %0, %1, %2;" : "=r"(r) : "f"(b), "f"(a));
    return r;
}
__device__ __forceinline__ void rot(float& c, float& s, float c1, float s1) {
    float t = fmaf(c, c1, -(s * s1));
    float u = fmaf(s, c1, c * s1);
    c = t; s = u;
}

#define STS128(a, v) asm volatile("st.shared.v4.b32 [%0], {%1,%2,%3,%4};" \
    :: "r"(a), "r"((v).x), "r"((v).y), "r"((v).z), "r"((v).w) : "memory")
#define LDSM4(r, addr) asm volatile( \
    "ldmatrix.sync.aligned.m8n8.x4.shared.b16 {%0,%1,%2,%3}, [%4];" \
    : "=r"((r)[0]), "=r"((r)[1]), "=r"((r)[2]), "=r"((r)[3]) : "r"(addr))
#define HMMA(d, a, b0v, b1v) asm volatile( \
    "mma.sync.aligned.m16n8k16.row.col.f32.f16.f16.f32 " \
    "{%0,%1,%2,%3}, {%4,%5,%6,%7}, {%8,%9}, {%0,%1,%2,%3};" \
    : "+f"((d)[0]), "+f"((d)[1]), "+f"((d)[2]), "+f"((d)[3]) \
    : "r"((a)[0]), "r"((a)[1]), "r"((a)[2]), "r"((a)[3]), "r"(b0v), "r"(b1v))

// ---------- kernel 1: sincos/silu transform ----------
__global__ void kan_xform(const float* __restrict__ x) {
    __shared__ float tx[32][33];
    int b0 = blockIdx.x * 32, i0 = blockIdx.y * 32;
    int tid = threadIdx.x;
#pragma unroll
    for (int it = 0; it < 4; ++it) {
        int idx = tid + it * 256;
        int bb = idx >> 5, ii = idx & 31;
        float v = x[(size_t)(b0 + bb) * Iq + i0 + ii];
        tx[bb][ii] = v;
        float sl = v / (1.0f + expf(-v));
        __half h = __float2half_rn(sl);
        g_bh[(size_t)(b0 + bb) * Iq + i0 + ii] = *reinterpret_cast<unsigned short*>(&h);
    }
    __syncthreads();
#pragma unroll
    for (int it = 0; it < 4; ++it) {
        int idx = tid + it * 256;
        int ii = idx >> 5, bb = idx & 31;
        float v = tx[bb][ii];
        float s, c;
        sincosf(v, &s, &c);
        size_t o = (size_t)(i0 + ii) * Bq + b0 + bb;
        g_c1[o] = c; g_s1[o] = s;
        sincosf(17.0f * v, &s, &c);
        g_c17[o] = c; g_s17[o] = s;
    }
}

// ---------- kernel 2: fold + fp16 hi/lo split of weights ----------
__global__ void kan_prep(const float* __restrict__ fc, const float* __restrict__ mask,
                         const float* __restrict__ sb, const float* __restrict__ sf) {
    int blk = blockIdx.x, j = threadIdx.x;
    unsigned short* dh = g_Wh + ((size_t)blk * Oq + j) * 64;
    unsigned short* dl = g_Wl + ((size_t)blk * Oq + j) * 64;
    if (blk < Iq) {
        int i = blk;
        float m = mask[i * Oq + j];
        float wf = sf[i * Oq + j] * m;
        const float* f0 = fc + ((size_t)j * Iq + i) * 32;
        const float* f1 = f0 + (size_t)Oq * Iq * 32;
        for (int g = 0; g < 8; ++g) {
            uint4 vh, vl;
            uint32_t* ph = &vh.x; uint32_t* pl = &vl.x;
            for (int e = 0; e < 4; ++e) {
                int s0 = g * 8 + 2 * e;
                float w0 = (s0 < 32) ? wf * f0[s0] : wf * f1[s0 - 32];
                float w1 = (s0 + 1 < 32) ? wf * f0[s0 + 1] : wf * f1[s0 - 31];
                uint32_t hp = h2pack(w0, w1);
                __half2 hh = *reinterpret_cast<__half2*>(&hp);
                float2 hf = __half22float2(hh);
                ph[e] = hp;
                pl[e] = h2pack(w0 - hf.x, w1 - hf.y);
            }
            *reinterpret_cast<uint4*>(dh + g * 8) = vh;
            *reinterpret_cast<uint4*>(dl + g * 8) = vl;
        }
    } else {
        int cb = blk - Iq;
        for (int g = 0; g < 8; ++g) {
            uint4 vh, vl;
            uint32_t* ph = &vh.x; uint32_t* pl = &vl.x;
            for (int e = 0; e < 4; ++e) {
                int s0 = g * 8 + 2 * e;
                int ia = cb * 64 + s0, ib = ia + 1;
                float w0 = mask[ia * Oq + j] * sb[ia * Oq + j];
                float w1 = mask[ib * Oq + j] * sb[ib * Oq + j];
                uint32_t hp = h2pack(w0, w1);
                __half2 hh = *reinterpret_cast<__half2*>(&hp);
                float2 hf = __half22float2(hh);
                ph[e] = hp;
                pl[e] = h2pack(w0 - hf.x, w1 - hf.y);
            }
            *reinterpret_cast<uint4*>(dh + g * 8) = vh;
            *reinterpret_cast<uint4*>(dl + g * 8) = vl;
        }
    }
}

// ---------- kernel 3: HMMA fused GEMM (fp16, W-compensated) ----------
__global__ void __launch_bounds__(256, 1)
kan_gemm(const float* __restrict__ bias, float* __restrict__ out) {
    extern __shared__ char smem[];
    const uint32_t sbase = (smem_u32(smem) + 127) & ~127u;

    const int tid = threadIdx.x, lane = tid & 31, wid = tid >> 5;
    const int wm = wid & 3, wn = wid >> 2;          // warp grid 4m x 2n
    const int b0 = blockIdx.x * 128, o0 = blockIdx.y * 64;

    const int gm = tid >> 1, gh = tid & 1;          // A-gen: row, half
    const int wrow = tid >> 2, wq = tid & 3;        // W-load: n-row, quarter

    float acc[2][4][4];
#pragma unroll
    for (int mt = 0; mt < 2; ++mt)
#pragma unroll
        for (int nf = 0; nf < 4; ++nf)
#pragma unroll
            for (int e = 0; e < 4; ++e) acc[mt][nf][e] = 0.0f;

    uint32_t aH[16];
    uint4 wR[4];
    float sd_c1, sd_s1, sd_cc, sd_ss;

    // --- prologue: seeds + W for chunk 0, generate A(0) ---
    {
        size_t gb = (size_t)0 * Bq + b0 + gm;
        sd_c1 = g_c1[gb]; sd_s1 = g_s1[gb];
        if (gh) { sd_cc = g_c17[gb]; sd_ss = g_s17[gb]; }
        else    { sd_cc = sd_c1;     sd_ss = sd_s1; }
        const uint4* ph = (const uint4*)(g_Wh + ((size_t)0 * Oq + o0 + wrow) * 64 + wq * 16);
        const uint4* pl = (const uint4*)(g_Wl + ((size_t)0 * Oq + o0 + wrow) * 64 + wq * 16);
        wR[0] = ph[0]; wR[1] = ph[1]; wR[2] = pl[0]; wR[3] = pl[1];
        float cc = sd_cc, ss = sd_ss;
#pragma unroll
        for (int p = 0; p < 8; ++p) {
            float ca = cc, sa = ss; rot(cc, ss, sd_c1, sd_s1);
            float cb = cc, sb2 = ss; rot(cc, ss, sd_c1, sd_s1);
            aH[p]     = h2pack(ca, cb);
            aH[8 + p] = h2pack(sa, sb2);
        }
    }

    const uint32_t arow = (uint32_t)gm * 128;
    const uint32_t wroff = (uint32_t)wrow * 128 + wq * 32;
    const uint32_t aoff = (uint32_t)(wm * 32 + (lane & 15)) * 128 + (lane >> 4) * 16;
    const uint32_t boff = (uint32_t)(wn * 32 + (lane & 7) + ((lane >> 4) << 3)) * 128
                        + ((lane >> 3) & 1) * 16;

    for (int c = 0; c < NCH; ++c) {
        const uint32_t st = sbase + (c & 1) * STG;

        __syncthreads();   // stage (c&1) free

        // ---- STS A (this thread: cos slots 16gh.., sin slots 32+16gh..) ----
        STS128(st + AHo + swz(arow + 32 * gh),       make_uint4(aH[0], aH[1], aH[2], aH[3]));
        STS128(st + AHo + swz(arow + 32 * gh + 16),  make_uint4(aH[4], aH[5], aH[6], aH[7]));
        STS128(st + AHo + swz(arow + 64 + 32 * gh),      make_uint4(aH[8], aH[9], aH[10], aH[11]));
        STS128(st + AHo + swz(arow + 64 + 32 * gh + 16), make_uint4(aH[12], aH[13], aH[14], aH[15]));
        // ---- STS W ----
        STS128(st + WHo + swz(wroff),      wR[0]);
        STS128(st + WHo + swz(wroff + 16), wR[1]);
        STS128(st + WLo + swz(wroff),      wR[2]);
        STS128(st + WLo + swz(wroff + 16), wR[3]);

        __syncthreads();   // stage (c&1) full

        // ---- prefetch chunk c+1 ----
        const int cn = c + 1;
        if (cn < NCH) {
            const uint4* ph = (const uint4*)(g_Wh + ((size_t)cn * Oq + o0 + wrow) * 64 + wq * 16);
            const uint4* pl = (const uint4*)(g_Wl + ((size_t)cn * Oq + o0 + wrow) * 64 + wq * 16);
            wR[0] = ph[0]; wR[1] = ph[1]; wR[2] = pl[0]; wR[3] = pl[1];
            if (cn < Iq) {
                size_t gb = (size_t)cn * Bq + b0 + gm;
                sd_c1 = g_c1[gb]; sd_s1 = g_s1[gb];
                if (gh) { sd_cc = g_c17[gb]; sd_ss = g_s17[gb]; }
                else    { sd_cc = sd_c1;     sd_ss = sd_s1; }
            }
        }

        // ---- MMA on chunk c ----
#pragma unroll
        for (int kk = 0; kk < 4; ++kk) {
            uint32_t a0[4], a1[4], wh0[4], wh1[4], wl0[4], wl1[4];
            LDSM4(a0,  st + AHo + swz(aoff + kk * 32));
            LDSM4(a1,  st + AHo + swz(aoff + 2048 + kk * 32));
            LDSM4(wh0, st + WHo + swz(boff + kk * 32));
            LDSM4(wh1, st + WHo + swz(boff + 2048 + kk * 32));
            LDSM4(wl0, st + WLo + swz(boff + kk * 32));
            LDSM4(wl1, st + WLo + swz(boff + 2048 + kk * 32));
#pragma unroll
            for (int mt = 0; mt < 2; ++mt) {
                const uint32_t* A = mt ? a1 : a0;
                HMMA(acc[mt][0], A, wh0[0], wh0[1]);
                HMMA(acc[mt][0], A, wl0[0], wl0[1]);
                HMMA(acc[mt][1], A, wh0[2], wh0[3]);
                HMMA(acc[mt][1], A, wl0[2], wl0[3]);
                HMMA(acc[mt][2], A, wh1[0], wh1[1]);
                HMMA(acc[mt][2], A, wl1[0], wl1[1]);
                HMMA(acc[mt][3], A, wh1[2], wh1[3]);
                HMMA(acc[mt][3], A, wl1[2], wl1[3]);
            }
        }

        // ---- generate A(c+1) ----
        if (cn < NCH) {
            if (cn < Iq) {
                float cc = sd_cc, ss = sd_ss;
#pragma unroll
                for (int p = 0; p < 8; ++p) {
                    float ca = cc, sa = ss; rot(cc, ss, sd_c1, sd_s1);
                    float cb = cc, sb2 = ss; rot(cc, ss, sd_c1, sd_s1);
                    aH[p]     = h2pack(ca, cb);
                    aH[8 + p] = h2pack(sa, sb2);
                }
            } else {
                int cb = cn - Iq;
                const unsigned short* ph = g_bh + (size_t)(b0 + gm) * Iq + cb * 64;
                uint4 v;
                v = *(const uint4*)(ph + 16 * gh);          aH[0]=v.x; aH[1]=v.y; aH[2]=v.z; aH[3]=v.w;
                v = *(const uint4*)(ph + 16 * gh + 8);      aH[4]=v.x; aH[5]=v.y; aH[6]=v.z; aH[7]=v.w;
                v = *(const uint4*)(ph + 32 + 16 * gh);     aH[8]=v.x; aH[9]=v.y; aH[10]=v.z; aH[11]=v.w;
                v = *(const uint4*)(ph + 32 + 16 * gh + 8); aH[12]=v.x; aH[13]=v.y; aH[14]=v.z; aH[15]=v.w;
            }
        }
    }

    // ---- epilogue ----
#pragma unroll
    for (int mt = 0; mt < 2; ++mt) {
#pragma unroll
        for (int nf = 0; nf < 4; ++nf) {
            int row = b0 + wm * 32 + mt * 16 + (lane >> 2);
            int col = o0 + wn * 32 + nf * 8 + 2 * (lane & 3);
            float bv0 = bias[col], bv1 = bias[col + 1];
            float2 v0 = make_float2(acc[mt][nf][0] + bv0, acc[mt][nf][1] + bv1);
            float2 v1 = make_float2(acc[mt][nf][2] + bv0, acc[mt][nf][3] + bv1);
            *reinterpret_cast<float2*>(out + (size_t)row * Oq + col) = v0;
            *reinterpret_cast<float2*>(out + (size_t)(row + 8) * Oq + col) = v1;
        }
    }
}

extern "C" void kernel_launch(void* const* d_in, const int* in_sizes, int n_in,
                              void* d_out, int out_size) {
    const float* x    = (const float*)d_in[0];
    const float* fc   = (const float*)d_in[1];
    const float* bias = (const float*)d_in[2];
    const float* mask = (const float*)d_in[3];
    const float* sb   = (const float*)d_in[4];
    const float* sf   = (const float*)d_in[5];
    float* out = (float*)d_out;

    cudaFuncSetAttribute(kan_gemm, cudaFuncAttributeMaxDynamicSharedMemorySize, GSMEM);

    kan_xform<<<dim3(Bq / 32, Iq / 32), 256>>>(x);
    kan_prep<<<NCH, Oq>>>(fc, mask, sb, sf);
    kan_gemm<<<dim3(Bq / 128, Oq / 64), 256, GSMEM>>>(bias, out);
}

// round 6
// speedup vs baseline: 3.9685x; 1.3293x over previous
#include <cuda_runtime.h>
#include <cuda_fp16.h>
#include <cstdint>

#define Bq 4096
#define Iq 256
#define Oq 256
#define NCH 260                 // 256 fourier chunks + 4 base chunks (K=64 each)
// stage layout: A 16K | W 8K
#define AHo 0
#define WHo 16384
#define STG 24576
#define GSMEM (2*STG + 1024)

// ---------- scratch (__device__ globals only) ----------
__device__ float g_c1[(size_t)Iq * Bq];
__device__ float g_s1[(size_t)Iq * Bq];
__device__ float g_c17[(size_t)Iq * Bq];
__device__ float g_s17[(size_t)Iq * Bq];
__device__ __align__(16) unsigned short g_bh[(size_t)Bq * Iq];       // silu fp16 [b][i]
__device__ __align__(16) unsigned short g_Wh[(size_t)NCH * Oq * 64]; // fp16 [chunk][j][slot]

// ---------- helpers ----------
__device__ __forceinline__ uint32_t smem_u32(const void* p) {
    uint32_t a;
    asm("{ .reg .u64 t; cvta.to.shared.u64 t, %1; cvt.u32.u64 %0, t; }" : "=r"(a) : "l"(p));
    return a;
}
__device__ __forceinline__ uint32_t swz(uint32_t off) { return off ^ ((off >> 3) & 0x70); }
__device__ __forceinline__ uint32_t h2pack(float a, float b) {  // a->low half
    uint32_t r;
    asm("cvt.rn.f16x2.f32 %0, %1, %2;" : "=r"(r) : "f"(b), "f"(a));
    return r;
}
__device__ __forceinline__ void rot(float& c, float& s, float c1, float s1) {
    float t = fmaf(c, c1, -(s * s1));
    float u = fmaf(s, c1, c * s1);
    c = t; s = u;
}

#define STS128(a, v) asm volatile("st.shared.v4.b32 [%0], {%1,%2,%3,%4};" \
    :: "r"(a), "r"((v).x), "r"((v).y), "r"((v).z), "r"((v).w) : "memory")
#define LDSM4(r, addr) asm volatile( \
    "ldmatrix.sync.aligned.m8n8.x4.shared.b16 {%0,%1,%2,%3}, [%4];" \
    : "=r"((r)[0]), "=r"((r)[1]), "=r"((r)[2]), "=r"((r)[3]) : "r"(addr))
#define HMMA(d, a, b0v, b1v) asm volatile( \
    "mma.sync.aligned.m16n8k16.row.col.f32.f16.f16.f32 " \
    "{%0,%1,%2,%3}, {%4,%5,%6,%7}, {%8,%9}, {%0,%1,%2,%3};" \
    : "+f"((d)[0]), "+f"((d)[1]), "+f"((d)[2]), "+f"((d)[3]) \
    : "r"((a)[0]), "r"((a)[1]), "r"((a)[2]), "r"((a)[3]), "r"(b0v), "r"(b1v))

// ---------- kernel 1: sincos/silu transform ----------
__global__ void kan_xform(const float* __restrict__ x) {
    __shared__ float tx[32][33];
    int b0 = blockIdx.x * 32, i0 = blockIdx.y * 32;
    int tid = threadIdx.x;
#pragma unroll
    for (int it = 0; it < 4; ++it) {
        int idx = tid + it * 256;
        int bb = idx >> 5, ii = idx & 31;
        float v = x[(size_t)(b0 + bb) * Iq + i0 + ii];
        tx[bb][ii] = v;
        float sl = v / (1.0f + expf(-v));
        __half h = __float2half_rn(sl);
        g_bh[(size_t)(b0 + bb) * Iq + i0 + ii] = *reinterpret_cast<unsigned short*>(&h);
    }
    __syncthreads();
#pragma unroll
    for (int it = 0; it < 4; ++it) {
        int idx = tid + it * 256;
        int ii = idx >> 5, bb = idx & 31;
        float v = tx[bb][ii];
        float s, c;
        sincosf(v, &s, &c);
        size_t o = (size_t)(i0 + ii) * Bq + b0 + bb;
        g_c1[o] = c; g_s1[o] = s;
        sincosf(17.0f * v, &s, &c);
        g_c17[o] = c; g_s17[o] = s;
    }
}

// ---------- kernel 2: fold weights -> fp16 ----------
__global__ void kan_prep(const float* __restrict__ fc, const float* __restrict__ mask,
                         const float* __restrict__ sb, const float* __restrict__ sf) {
    int blk = blockIdx.x, j = threadIdx.x;
    unsigned short* dh = g_Wh + ((size_t)blk * Oq + j) * 64;
    if (blk < Iq) {
        int i = blk;
        float m = mask[i * Oq + j];
        float wf = sf[i * Oq + j] * m;
        const float* f0 = fc + ((size_t)j * Iq + i) * 32;
        const float* f1 = f0 + (size_t)Oq * Iq * 32;
        for (int g = 0; g < 8; ++g) {
            uint4 vh;
            uint32_t* ph = &vh.x;
            for (int e = 0; e < 4; ++e) {
                int s0 = g * 8 + 2 * e;
                float w0 = (s0 < 32) ? wf * f0[s0] : wf * f1[s0 - 32];
                float w1 = (s0 + 1 < 32) ? wf * f0[s0 + 1] : wf * f1[s0 - 31];
                ph[e] = h2pack(w0, w1);
            }
            *reinterpret_cast<uint4*>(dh + g * 8) = vh;
        }
    } else {
        int cb = blk - Iq;
        for (int g = 0; g < 8; ++g) {
            uint4 vh;
            uint32_t* ph = &vh.x;
            for (int e = 0; e < 4; ++e) {
                int s0 = g * 8 + 2 * e;
                int ia = cb * 64 + s0, ib = ia + 1;
                float w0 = mask[ia * Oq + j] * sb[ia * Oq + j];
                float w1 = mask[ib * Oq + j] * sb[ib * Oq + j];
                ph[e] = h2pack(w0, w1);
            }
            *reinterpret_cast<uint4*>(dh + g * 8) = vh;
        }
    }
}

// ---------- kernel 3: HMMA fused GEMM (single fp16 term) ----------
__global__ void __launch_bounds__(256, 1)
kan_gemm(const float* __restrict__ bias, float* __restrict__ out) {
    extern __shared__ char smem[];
    const uint32_t sbase = (smem_u32(smem) + 127) & ~127u;

    const int tid = threadIdx.x, lane = tid & 31, wid = tid >> 5;
    const int wm = wid & 3, wn = wid >> 2;          // warp grid 4m x 2n
    const int b0 = blockIdx.x * 128, o0 = blockIdx.y * 64;

    const int gm = tid >> 1, gh = tid & 1;          // A-gen: row, half
    const int wrow = tid >> 2, wq = tid & 3;        // W-load: n-row, quarter

    float acc[2][4][4];
#pragma unroll
    for (int mt = 0; mt < 2; ++mt)
#pragma unroll
        for (int nf = 0; nf < 4; ++nf)
#pragma unroll
            for (int e = 0; e < 4; ++e) acc[mt][nf][e] = 0.0f;

    uint32_t aH[16];
    uint4 wR[2];
    float sd_c1, sd_s1, sd_cc, sd_ss;

    // --- prologue: seeds + W for chunk 0, generate A(0) ---
    {
        size_t gb = (size_t)0 * Bq + b0 + gm;
        sd_c1 = g_c1[gb]; sd_s1 = g_s1[gb];
        if (gh) { sd_cc = g_c17[gb]; sd_ss = g_s17[gb]; }
        else    { sd_cc = sd_c1;     sd_ss = sd_s1; }
        const uint4* ph = (const uint4*)(g_Wh + ((size_t)0 * Oq + o0 + wrow) * 64 + wq * 16);
        wR[0] = ph[0]; wR[1] = ph[1];
        float cc = sd_cc, ss = sd_ss;
#pragma unroll
        for (int p = 0; p < 8; ++p) {
            float ca = cc, sa = ss; rot(cc, ss, sd_c1, sd_s1);
            float cb = cc, sb2 = ss; rot(cc, ss, sd_c1, sd_s1);
            aH[p]     = h2pack(ca, cb);
            aH[8 + p] = h2pack(sa, sb2);
        }
    }

    const uint32_t arow = (uint32_t)gm * 128;
    const uint32_t wroff = (uint32_t)wrow * 128 + wq * 32;
    const uint32_t aoff = (uint32_t)(wm * 32 + (lane & 15)) * 128 + (lane >> 4) * 16;
    const uint32_t boff = (uint32_t)(wn * 32 + (lane & 7) + ((lane >> 4) << 3)) * 128
                        + ((lane >> 3) & 1) * 16;

    for (int c = 0; c < NCH; ++c) {
        const uint32_t st = sbase + (c & 1) * STG;

        __syncthreads();   // stage (c&1) free

        // ---- STS A ----
        STS128(st + AHo + swz(arow + 32 * gh),       make_uint4(aH[0], aH[1], aH[2], aH[3]));
        STS128(st + AHo + swz(arow + 32 * gh + 16),  make_uint4(aH[4], aH[5], aH[6], aH[7]));
        STS128(st + AHo + swz(arow + 64 + 32 * gh),      make_uint4(aH[8], aH[9], aH[10], aH[11]));
        STS128(st + AHo + swz(arow + 64 + 32 * gh + 16), make_uint4(aH[12], aH[13], aH[14], aH[15]));
        // ---- STS W ----
        STS128(st + WHo + swz(wroff),      wR[0]);
        STS128(st + WHo + swz(wroff + 16), wR[1]);

        __syncthreads();   // stage (c&1) full

        // ---- prefetch chunk c+1 ----
        const int cn = c + 1;
        if (cn < NCH) {
            const uint4* ph = (const uint4*)(g_Wh + ((size_t)cn * Oq + o0 + wrow) * 64 + wq * 16);
            wR[0] = ph[0]; wR[1] = ph[1];
            if (cn < Iq) {
                size_t gb = (size_t)cn * Bq + b0 + gm;
                sd_c1 = g_c1[gb]; sd_s1 = g_s1[gb];
                if (gh) { sd_cc = g_c17[gb]; sd_ss = g_s17[gb]; }
                else    { sd_cc = sd_c1;     sd_ss = sd_s1; }
            }
        }

        // ---- MMA on chunk c ----
#pragma unroll
        for (int kk = 0; kk < 4; ++kk) {
            uint32_t a0[4], a1[4], wh0[4], wh1[4];
            LDSM4(a0,  st + AHo + swz(aoff + kk * 32));
            LDSM4(a1,  st + AHo + swz(aoff + 2048 + kk * 32));
            LDSM4(wh0, st + WHo + swz(boff + kk * 32));
            LDSM4(wh1, st + WHo + swz(boff + 2048 + kk * 32));
#pragma unroll
            for (int mt = 0; mt < 2; ++mt) {
                const uint32_t* A = mt ? a1 : a0;
                HMMA(acc[mt][0], A, wh0[0], wh0[1]);
                HMMA(acc[mt][1], A, wh0[2], wh0[3]);
                HMMA(acc[mt][2], A, wh1[0], wh1[1]);
                HMMA(acc[mt][3], A, wh1[2], wh1[3]);
            }
        }

        // ---- generate A(c+1) ----
        if (cn < NCH) {
            if (cn < Iq) {
                float cc = sd_cc, ss = sd_ss;
#pragma unroll
                for (int p = 0; p < 8; ++p) {
                    float ca = cc, sa = ss; rot(cc, ss, sd_c1, sd_s1);
                    float cb = cc, sb2 = ss; rot(cc, ss, sd_c1, sd_s1);
                    aH[p]     = h2pack(ca, cb);
                    aH[8 + p] = h2pack(sa, sb2);
                }
            } else {
                int cb = cn - Iq;
                const unsigned short* ph = g_bh + (size_t)(b0 + gm) * Iq + cb * 64;
                uint4 v;
                v = *(const uint4*)(ph + 16 * gh);          aH[0]=v.x; aH[1]=v.y; aH[2]=v.z; aH[3]=v.w;
                v = *(const uint4*)(ph + 16 * gh + 8);      aH[4]=v.x; aH[5]=v.y; aH[6]=v.z; aH[7]=v.w;
                v = *(const uint4*)(ph + 32 + 16 * gh);     aH[8]=v.x; aH[9]=v.y; aH[10]=v.z; aH[11]=v.w;
                v = *(const uint4*)(ph + 32 + 16 * gh + 8); aH[12]=v.x; aH[13]=v.y; aH[14]=v.z; aH[15]=v.w;
            }
        }
    }

    // ---- epilogue ----
#pragma unroll
    for (int mt = 0; mt < 2; ++mt) {
#pragma unroll
        for (int nf = 0; nf < 4; ++nf) {
            int row = b0 + wm * 32 + mt * 16 + (lane >> 2);
            int col = o0 + wn * 32 + nf * 8 + 2 * (lane & 3);
            float bv0 = bias[col], bv1 = bias[col + 1];
            float2 v0 = make_float2(acc[mt][nf][0] + bv0, acc[mt][nf][1] + bv1);
            float2 v1 = make_float2(acc[mt][nf][2] + bv0, acc[mt][nf][3] + bv1);
            *reinterpret_cast<float2*>(out + (size_t)row * Oq + col) = v0;
            *reinterpret_cast<float2*>(out + (size_t)(row + 8) * Oq + col) = v1;
        }
    }
}

extern "C" void kernel_launch(void* const* d_in, const int* in_sizes, int n_in,
                              void* d_out, int out_size) {
    const float* x    = (const float*)d_in[0];
    const float* fc   = (const float*)d_in[1];
    const float* bias = (const float*)d_in[2];
    const float* mask = (const float*)d_in[3];
    const float* sb   = (const float*)d_in[4];
    const float* sf   = (const float*)d_in[5];
    float* out = (float*)d_out;

    cudaFuncSetAttribute(kan_gemm, cudaFuncAttributeMaxDynamicSharedMemorySize, GSMEM);

    kan_xform<<<dim3(Bq / 32, Iq / 32), 256>>>(x);
    kan_prep<<<NCH, Oq>>>(fc, mask, sb, sf);
    kan_gemm<<<dim3(Bq / 128, Oq / 64), 256, GSMEM>>>(bias, out);
}

// round 7
// speedup vs baseline: 4.3172x; 1.0879x over previous
#include <cuda_runtime.h>
#include <cuda_fp16.h>
#include <cstdint>

#define Bq 4096
#define Iq 256
#define Oq 256
#define NCH 260                 // 256 fourier chunks + 4 base chunks (K=64 each)
// stage layout: A 16K | W 8K
#define AHo 0
#define WHo 16384
#define STG 24576
#define GSMEM (2*STG + 1024)

// ---------- scratch (__device__ globals only) ----------
__device__ float g_c1[(size_t)Iq * Bq];
__device__ float g_s1[(size_t)Iq * Bq];
__device__ float g_c17[(size_t)Iq * Bq];
__device__ float g_s17[(size_t)Iq * Bq];
__device__ __align__(16) unsigned short g_bh[(size_t)Bq * Iq];       // silu fp16 [b][i]
__device__ __align__(16) unsigned short g_Wh[(size_t)NCH * Oq * 64]; // fp16 [chunk][j][slot]

// ---------- helpers ----------
__device__ __forceinline__ uint32_t smem_u32(const void* p) {
    uint32_t a;
    asm("{ .reg .u64 t; cvta.to.shared.u64 t, %1; cvt.u32.u64 %0, t; }" : "=r"(a) : "l"(p));
    return a;
}
__device__ __forceinline__ uint32_t swz(uint32_t off) { return off ^ ((off >> 3) & 0x70); }
__device__ __forceinline__ uint32_t h2pack(float a, float b) {  // a->low half
    uint32_t r;
    asm("cvt.rn.f16x2.f32 %0, %1, %2;" : "=r"(r) : "f"(b), "f"(a));
    return r;
}
__device__ __forceinline__ void rot(float& c, float& s, float c1, float s1) {
    float t = fmaf(c, c1, -(s * s1));
    float u = fmaf(s, c1, c * s1);
    c = t; s = u;
}

#define STS128(a, v) asm volatile("st.shared.v4.b32 [%0], {%1,%2,%3,%4};" \
    :: "r"(a), "r"((v).x), "r"((v).y), "r"((v).z), "r"((v).w) : "memory")
#define LDSM4(r, addr) asm volatile( \
    "ldmatrix.sync.aligned.m8n8.x4.shared.b16 {%0,%1,%2,%3}, [%4];" \
    : "=r"((r)[0]), "=r"((r)[1]), "=r"((r)[2]), "=r"((r)[3]) : "r"(addr))
#define HMMA(d, a, b0v, b1v) asm volatile( \
    "mma.sync.aligned.m16n8k16.row.col.f32.f16.f16.f32 " \
    "{%0,%1,%2,%3}, {%4,%5,%6,%7}, {%8,%9}, {%0,%1,%2,%3};" \
    : "+f"((d)[0]), "+f"((d)[1]), "+f"((d)[2]), "+f"((d)[3]) \
    : "r"((a)[0]), "r"((a)[1]), "r"((a)[2]), "r"((a)[3]), "r"(b0v), "r"(b1v))

// ---------- kernel 1: sincos/silu transform ----------
__global__ void kan_xform(const float* __restrict__ x) {
    __shared__ float tx[32][33];
    int b0 = blockIdx.x * 32, i0 = blockIdx.y * 32;
    int tid = threadIdx.x;
#pragma unroll
    for (int it = 0; it < 4; ++it) {
        int idx = tid + it * 256;
        int bb = idx >> 5, ii = idx & 31;
        float v = x[(size_t)(b0 + bb) * Iq + i0 + ii];
        tx[bb][ii] = v;
        float sl = v / (1.0f + expf(-v));
        __half h = __float2half_rn(sl);
        g_bh[(size_t)(b0 + bb) * Iq + i0 + ii] = *reinterpret_cast<unsigned short*>(&h);
    }
    __syncthreads();
#pragma unroll
    for (int it = 0; it < 4; ++it) {
        int idx = tid + it * 256;
        int ii = idx >> 5, bb = idx & 31;
        float v = tx[bb][ii];
        float s, c;
        sincosf(v, &s, &c);
        size_t o = (size_t)(i0 + ii) * Bq + b0 + bb;
        g_c1[o] = c; g_s1[o] = s;
        sincosf(17.0f * v, &s, &c);
        g_c17[o] = c; g_s17[o] = s;
    }
}

// ---------- kernel 2: fold weights -> fp16 ----------
__global__ void kan_prep(const float* __restrict__ fc, const float* __restrict__ mask,
                         const float* __restrict__ sb, const float* __restrict__ sf) {
    int blk = blockIdx.x, j = threadIdx.x;
    unsigned short* dh = g_Wh + ((size_t)blk * Oq + j) * 64;
    if (blk < Iq) {
        int i = blk;
        float m = mask[i * Oq + j];
        float wf = sf[i * Oq + j] * m;
        const float* f0 = fc + ((size_t)j * Iq + i) * 32;
        const float* f1 = f0 + (size_t)Oq * Iq * 32;
        for (int g = 0; g < 8; ++g) {
            uint4 vh;
            uint32_t* ph = &vh.x;
            for (int e = 0; e < 4; ++e) {
                int s0 = g * 8 + 2 * e;
                float w0 = (s0 < 32) ? wf * f0[s0] : wf * f1[s0 - 32];
                float w1 = (s0 + 1 < 32) ? wf * f0[s0 + 1] : wf * f1[s0 - 31];
                ph[e] = h2pack(w0, w1);
            }
            *reinterpret_cast<uint4*>(dh + g * 8) = vh;
        }
    } else {
        int cb = blk - Iq;
        for (int g = 0; g < 8; ++g) {
            uint4 vh;
            uint32_t* ph = &vh.x;
            for (int e = 0; e < 4; ++e) {
                int s0 = g * 8 + 2 * e;
                int ia = cb * 64 + s0, ib = ia + 1;
                float w0 = mask[ia * Oq + j] * sb[ia * Oq + j];
                float w1 = mask[ib * Oq + j] * sb[ib * Oq + j];
                ph[e] = h2pack(w0, w1);
            }
            *reinterpret_cast<uint4*>(dh + g * 8) = vh;
        }
    }
}

// ---------- kernel 3: HMMA fused GEMM, single barrier per chunk ----------
__global__ void __launch_bounds__(256, 1)
kan_gemm(const float* __restrict__ bias, float* __restrict__ out) {
    extern __shared__ char smem[];
    const uint32_t sbase = (smem_u32(smem) + 127) & ~127u;

    const int tid = threadIdx.x, lane = tid & 31, wid = tid >> 5;
    const int wm = wid & 3, wn = wid >> 2;          // warp grid 4m x 2n
    const int b0 = blockIdx.x * 128, o0 = blockIdx.y * 64;

    const int gm = tid >> 1, gh = tid & 1;          // A-gen: row, half
    const int wrow = tid >> 2, wq = tid & 3;        // W-load: n-row, quarter

    float acc[2][4][4];
#pragma unroll
    for (int mt = 0; mt < 2; ++mt)
#pragma unroll
        for (int nf = 0; nf < 4; ++nf)
#pragma unroll
            for (int e = 0; e < 4; ++e) acc[mt][nf][e] = 0.0f;

    uint32_t aH[16];
    uint4 wR[2];
    float sd_c1, sd_s1, sd_cc, sd_ss;

    const uint32_t arow = (uint32_t)gm * 128;
    const uint32_t wroff = (uint32_t)wrow * 128 + wq * 32;
    const uint32_t aoff = (uint32_t)(wm * 32 + (lane & 15)) * 128 + (lane >> 4) * 16;
    const uint32_t boff = (uint32_t)(wn * 32 + (lane & 7) + ((lane >> 4) << 3)) * 128
                        + ((lane >> 3) & 1) * 16;

    // --- prologue: seeds + W for chunk 0, generate A(0), STS into stage 0 ---
    {
        size_t gb = (size_t)0 * Bq + b0 + gm;
        sd_c1 = g_c1[gb]; sd_s1 = g_s1[gb];
        if (gh) { sd_cc = g_c17[gb]; sd_ss = g_s17[gb]; }
        else    { sd_cc = sd_c1;     sd_ss = sd_s1; }
        const uint4* ph = (const uint4*)(g_Wh + ((size_t)0 * Oq + o0 + wrow) * 64 + wq * 16);
        wR[0] = ph[0]; wR[1] = ph[1];
        float cc = sd_cc, ss = sd_ss;
#pragma unroll
        for (int p = 0; p < 8; ++p) {
            float ca = cc, sa = ss; rot(cc, ss, sd_c1, sd_s1);
            float cb = cc, sb2 = ss; rot(cc, ss, sd_c1, sd_s1);
            aH[p]     = h2pack(ca, cb);
            aH[8 + p] = h2pack(sa, sb2);
        }
        const uint32_t st = sbase;
        STS128(st + AHo + swz(arow + 32 * gh),           make_uint4(aH[0], aH[1], aH[2], aH[3]));
        STS128(st + AHo + swz(arow + 32 * gh + 16),      make_uint4(aH[4], aH[5], aH[6], aH[7]));
        STS128(st + AHo + swz(arow + 64 + 32 * gh),      make_uint4(aH[8], aH[9], aH[10], aH[11]));
        STS128(st + AHo + swz(arow + 64 + 32 * gh + 16), make_uint4(aH[12], aH[13], aH[14], aH[15]));
        STS128(st + WHo + swz(wroff),      wR[0]);
        STS128(st + WHo + swz(wroff + 16), wR[1]);
    }

    for (int c = 0; c < NCH; ++c) {
        const uint32_t st = sbase + (c & 1) * STG;

        __syncthreads();   // STS(c) visible; stage s^1 free for writing

        const int cn = c + 1;
        // ---- issue global prefetch for chunk c+1 early (hidden under MMA) ----
        if (cn < NCH) {
            const uint4* ph = (const uint4*)(g_Wh + ((size_t)cn * Oq + o0 + wrow) * 64 + wq * 16);
            wR[0] = ph[0]; wR[1] = ph[1];
            if (cn < Iq) {
                size_t gb = (size_t)cn * Bq + b0 + gm;
                sd_c1 = g_c1[gb]; sd_s1 = g_s1[gb];
                if (gh) { sd_cc = g_c17[gb]; sd_ss = g_s17[gb]; }
                else    { sd_cc = sd_c1;     sd_ss = sd_s1; }
            }
        }

        // ---- MMA on chunk c ----
#pragma unroll
        for (int kk = 0; kk < 4; ++kk) {
            uint32_t a0[4], a1[4], wh0[4], wh1[4];
            LDSM4(a0,  st + AHo + swz(aoff + kk * 32));
            LDSM4(a1,  st + AHo + swz(aoff + 2048 + kk * 32));
            LDSM4(wh0, st + WHo + swz(boff + kk * 32));
            LDSM4(wh1, st + WHo + swz(boff + 2048 + kk * 32));
#pragma unroll
            for (int mt = 0; mt < 2; ++mt) {
                const uint32_t* A = mt ? a1 : a0;
                HMMA(acc[mt][0], A, wh0[0], wh0[1]);
                HMMA(acc[mt][1], A, wh0[2], wh0[3]);
                HMMA(acc[mt][2], A, wh1[0], wh1[1]);
                HMMA(acc[mt][3], A, wh1[2], wh1[3]);
            }
        }

        // ---- generate + STS chunk c+1 into stage s^1 (overlaps MMA issue) ----
        if (cn < NCH) {
            if (cn < Iq) {
                float cc = sd_cc, ss = sd_ss;
#pragma unroll
                for (int p = 0; p < 8; ++p) {
                    float ca = cc, sa = ss; rot(cc, ss, sd_c1, sd_s1);
                    float cb = cc, sb2 = ss; rot(cc, ss, sd_c1, sd_s1);
                    aH[p]     = h2pack(ca, cb);
                    aH[8 + p] = h2pack(sa, sb2);
                }
            } else {
                int cb = cn - Iq;
                const unsigned short* ph = g_bh + (size_t)(b0 + gm) * Iq + cb * 64;
                uint4 v;
                v = *(const uint4*)(ph + 16 * gh);          aH[0]=v.x; aH[1]=v.y; aH[2]=v.z; aH[3]=v.w;
                v = *(const uint4*)(ph + 16 * gh + 8);      aH[4]=v.x; aH[5]=v.y; aH[6]=v.z; aH[7]=v.w;
                v = *(const uint4*)(ph + 32 + 16 * gh);     aH[8]=v.x; aH[9]=v.y; aH[10]=v.z; aH[11]=v.w;
                v = *(const uint4*)(ph + 32 + 16 * gh + 8); aH[12]=v.x; aH[13]=v.y; aH[14]=v.z; aH[15]=v.w;
            }
            const uint32_t sn = sbase + (cn & 1) * STG;
            STS128(sn + AHo + swz(arow + 32 * gh),           make_uint4(aH[0], aH[1], aH[2], aH[3]));
            STS128(sn + AHo + swz(arow + 32 * gh + 16),      make_uint4(aH[4], aH[5], aH[6], aH[7]));
            STS128(sn + AHo + swz(arow + 64 + 32 * gh),      make_uint4(aH[8], aH[9], aH[10], aH[11]));
            STS128(sn + AHo + swz(arow + 64 + 32 * gh + 16), make_uint4(aH[12], aH[13], aH[14], aH[15]));
            STS128(sn + WHo + swz(wroff),      wR[0]);
            STS128(sn + WHo + swz(wroff + 16), wR[1]);
        }
    }

    // ---- epilogue ----
#pragma unroll
    for (int mt = 0; mt < 2; ++mt) {
#pragma unroll
        for (int nf = 0; nf < 4; ++nf) {
            int row = b0 + wm * 32 + mt * 16 + (lane >> 2);
            int col = o0 + wn * 32 + nf * 8 + 2 * (lane & 3);
            float bv0 = bias[col], bv1 = bias[col + 1];
            float2 v0 = make_float2(acc[mt][nf][0] + bv0, acc[mt][nf][1] + bv1);
            float2 v1 = make_float2(acc[mt][nf][2] + bv0, acc[mt][nf][3] + bv1);
            *reinterpret_cast<float2*>(out + (size_t)row * Oq + col) = v0;
            *reinterpret_cast<float2*>(out + (size_t)(row + 8) * Oq + col) = v1;
        }
    }
}

extern "C" void kernel_launch(void* const* d_in, const int* in_sizes, int n_in,
                              void* d_out, int out_size) {
    const float* x    = (const float*)d_in[0];
    const float* fc   = (const float*)d_in[1];
    const float* bias = (const float*)d_in[2];
    const float* mask = (const float*)d_in[3];
    const float* sb   = (const float*)d_in[4];
    const float* sf   = (const float*)d_in[5];
    float* out = (float*)d_out;

    cudaFuncSetAttribute(kan_gemm, cudaFuncAttributeMaxDynamicSharedMemorySize, GSMEM);

    kan_xform<<<dim3(Bq / 32, Iq / 32), 256>>>(x);
    kan_prep<<<NCH, Oq>>>(fc, mask, sb, sf);
    kan_gemm<<<dim3(Bq / 128, Oq / 64), 256, GSMEM>>>(bias, out);
}

// round 8
// speedup vs baseline: 4.3884x; 1.0165x over previous
#include <cuda_runtime.h>
#include <cuda_fp16.h>
#include <cstdint>

#define Bq 4096
#define Iq 256
#define Oq 256
#define NCH 260                 // 256 fourier chunks + 4 base chunks (K=64 each)
#define NCP 130                 // chunk pairs per CTA
// stage layout: A0 16K | A1 16K | W0 8K | W1 8K
#define A0o 0
#define A1o 16384
#define W0o 32768
#define W1o 40960
#define STG 49152
#define GSMEM (2*STG + 1024)

// ---------- scratch (__device__ globals only) ----------
__device__ float g_c1[(size_t)Iq * Bq];
__device__ float g_s1[(size_t)Iq * Bq];
__device__ float g_c17[(size_t)Iq * Bq];
__device__ float g_s17[(size_t)Iq * Bq];
__device__ __align__(16) unsigned short g_bh[(size_t)Bq * Iq];       // silu fp16 [b][i]
__device__ __align__(16) unsigned short g_Wh[(size_t)NCH * Oq * 64]; // fp16 [chunk][j][slot]

// ---------- helpers ----------
__device__ __forceinline__ uint32_t smem_u32(const void* p) {
    uint32_t a;
    asm("{ .reg .u64 t; cvta.to.shared.u64 t, %1; cvt.u32.u64 %0, t; }" : "=r"(a) : "l"(p));
    return a;
}
__device__ __forceinline__ uint32_t swz(uint32_t off) { return off ^ ((off >> 3) & 0x70); }
__device__ __forceinline__ uint32_t h2pack(float a, float b) {  // a->low half
    uint32_t r;
    asm("cvt.rn.f16x2.f32 %0, %1, %2;" : "=r"(r) : "f"(b), "f"(a));
    return r;
}
__device__ __forceinline__ void rot(float& c, float& s, float c1, float s1) {
    float t = fmaf(c, c1, -(s * s1));
    float u = fmaf(s, c1, c * s1);
    c = t; s = u;
}

#define STS128(a, v) asm volatile("st.shared.v4.b32 [%0], {%1,%2,%3,%4};" \
    :: "r"(a), "r"((v).x), "r"((v).y), "r"((v).z), "r"((v).w) : "memory")
#define LDSM4(r, addr) asm volatile( \
    "ldmatrix.sync.aligned.m8n8.x4.shared.b16 {%0,%1,%2,%3}, [%4];" \
    : "=r"((r)[0]), "=r"((r)[1]), "=r"((r)[2]), "=r"((r)[3]) : "r"(addr))
#define HMMA(d, a, b0v, b1v) asm volatile( \
    "mma.sync.aligned.m16n8k16.row.col.f32.f16.f16.f32 " \
    "{%0,%1,%2,%3}, {%4,%5,%6,%7}, {%8,%9}, {%0,%1,%2,%3};" \
    : "+f"((d)[0]), "+f"((d)[1]), "+f"((d)[2]), "+f"((d)[3]) \
    : "r"((a)[0]), "r"((a)[1]), "r"((a)[2]), "r"((a)[3]), "r"(b0v), "r"(b1v))

// ---------- kernel 1: sincos/silu transform ----------
__global__ void kan_xform(const float* __restrict__ x) {
    __shared__ float tx[32][33];
    int b0 = blockIdx.x * 32, i0 = blockIdx.y * 32;
    int tid = threadIdx.x;
#pragma unroll
    for (int it = 0; it < 4; ++it) {
        int idx = tid + it * 256;
        int bb = idx >> 5, ii = idx & 31;
        float v = x[(size_t)(b0 + bb) * Iq + i0 + ii];
        tx[bb][ii] = v;
        float sl = v / (1.0f + expf(-v));
        __half h = __float2half_rn(sl);
        g_bh[(size_t)(b0 + bb) * Iq + i0 + ii] = *reinterpret_cast<unsigned short*>(&h);
    }
    __syncthreads();
#pragma unroll
    for (int it = 0; it < 4; ++it) {
        int idx = tid + it * 256;
        int ii = idx >> 5, bb = idx & 31;
        float v = tx[bb][ii];
        float s, c;
        sincosf(v, &s, &c);
        size_t o = (size_t)(i0 + ii) * Bq + b0 + bb;
        g_c1[o] = c; g_s1[o] = s;
        sincosf(17.0f * v, &s, &c);
        g_c17[o] = c; g_s17[o] = s;
    }
}

// ---------- kernel 2: fold weights -> fp16 ----------
__global__ void kan_prep(const float* __restrict__ fc, const float* __restrict__ mask,
                         const float* __restrict__ sb, const float* __restrict__ sf) {
    int blk = blockIdx.x, j = threadIdx.x;
    unsigned short* dh = g_Wh + ((size_t)blk * Oq + j) * 64;
    if (blk < Iq) {
        int i = blk;
        float m = mask[i * Oq + j];
        float wf = sf[i * Oq + j] * m;
        const float* f0 = fc + ((size_t)j * Iq + i) * 32;
        const float* f1 = f0 + (size_t)Oq * Iq * 32;
        for (int g = 0; g < 8; ++g) {
            uint4 vh;
            uint32_t* ph = &vh.x;
            for (int e = 0; e < 4; ++e) {
                int s0 = g * 8 + 2 * e;
                float w0 = (s0 < 32) ? wf * f0[s0] : wf * f1[s0 - 32];
                float w1 = (s0 + 1 < 32) ? wf * f0[s0 + 1] : wf * f1[s0 - 31];
                ph[e] = h2pack(w0, w1);
            }
            *reinterpret_cast<uint4*>(dh + g * 8) = vh;
        }
    } else {
        int cb = blk - Iq;
        for (int g = 0; g < 8; ++g) {
            uint4 vh;
            uint32_t* ph = &vh.x;
            for (int e = 0; e < 4; ++e) {
                int s0 = g * 8 + 2 * e;
                int ia = cb * 64 + s0, ib = ia + 1;
                float w0 = mask[ia * Oq + j] * sb[ia * Oq + j];
                float w1 = mask[ib * Oq + j] * sb[ib * Oq + j];
                ph[e] = h2pack(w0, w1);
            }
            *reinterpret_cast<uint4*>(dh + g * 8) = vh;
        }
    }
}

// ---------- kernel 3: HMMA fused GEMM, K=128 per barrier ----------
__global__ void __launch_bounds__(256, 1)
kan_gemm(const float* __restrict__ bias, float* __restrict__ out) {
    extern __shared__ char smem[];
    const uint32_t sbase = (smem_u32(smem) + 127) & ~127u;

    const int tid = threadIdx.x, lane = tid & 31, wid = tid >> 5;
    const int wm = wid & 3, wn = wid >> 2;          // warp grid 4m x 2n
    const int b0 = blockIdx.x * 128, o0 = blockIdx.y * 64;

    const int gm = tid >> 1, gh = tid & 1;          // A-gen: row, half
    const int wrow = tid >> 2, wq = tid & 3;        // W-load: n-row, quarter

    float acc[2][4][4];
#pragma unroll
    for (int mt = 0; mt < 2; ++mt)
#pragma unroll
        for (int nf = 0; nf < 4; ++nf)
#pragma unroll
            for (int e = 0; e < 4; ++e) acc[mt][nf][e] = 0.0f;

    const uint32_t arow = (uint32_t)gm * 128;
    const uint32_t wroff = (uint32_t)wrow * 128 + wq * 32;
    const uint32_t aoff = (uint32_t)(wm * 32 + (lane & 15)) * 128 + (lane >> 4) * 16;
    const uint32_t boff = (uint32_t)(wn * 32 + (lane & 7) + ((lane >> 4) << 3)) * 128
                        + ((lane >> 3) & 1) * 16;

    // ---- helper lambdas ----
    auto genA = [&](int cn, uint32_t aBase, float c1s, float s1s, float ccs, float sss) {
        uint32_t aH[16];
        if (cn < Iq) {
            float cc = ccs, ss = sss;
#pragma unroll
            for (int p = 0; p < 8; ++p) {
                float ca = cc, sa = ss; rot(cc, ss, c1s, s1s);
                float cb = cc, sb2 = ss; rot(cc, ss, c1s, s1s);
                aH[p]     = h2pack(ca, cb);
                aH[8 + p] = h2pack(sa, sb2);
            }
        } else {
            int cb = cn - Iq;
            const unsigned short* ph = g_bh + (size_t)(b0 + gm) * Iq + cb * 64;
            uint4 v;
            v = *(const uint4*)(ph + 16 * gh);          aH[0]=v.x; aH[1]=v.y; aH[2]=v.z; aH[3]=v.w;
            v = *(const uint4*)(ph + 16 * gh + 8);      aH[4]=v.x; aH[5]=v.y; aH[6]=v.z; aH[7]=v.w;
            v = *(const uint4*)(ph + 32 + 16 * gh);     aH[8]=v.x; aH[9]=v.y; aH[10]=v.z; aH[11]=v.w;
            v = *(const uint4*)(ph + 32 + 16 * gh + 8); aH[12]=v.x; aH[13]=v.y; aH[14]=v.z; aH[15]=v.w;
        }
        STS128(aBase + swz(arow + 32 * gh),           make_uint4(aH[0], aH[1], aH[2], aH[3]));
        STS128(aBase + swz(arow + 32 * gh + 16),      make_uint4(aH[4], aH[5], aH[6], aH[7]));
        STS128(aBase + swz(arow + 64 + 32 * gh),      make_uint4(aH[8], aH[9], aH[10], aH[11]));
        STS128(aBase + swz(arow + 64 + 32 * gh + 16), make_uint4(aH[12], aH[13], aH[14], aH[15]));
    };

    // ---- prologue: pair 0 into stage 0 ----
    {
        float c1s[2], s1s[2], ccs[2], sss[2];
        uint4 wRp[4];
#pragma unroll
        for (int k = 0; k < 2; ++k) {
            size_t gb = (size_t)k * Bq + b0 + gm;
            c1s[k] = g_c1[gb]; s1s[k] = g_s1[gb];
            if (gh) { ccs[k] = g_c17[gb]; sss[k] = g_s17[gb]; }
            else    { ccs[k] = c1s[k];    sss[k] = s1s[k]; }
            const uint4* ph = (const uint4*)(g_Wh + ((size_t)k * Oq + o0 + wrow) * 64 + wq * 16);
            wRp[2 * k] = ph[0]; wRp[2 * k + 1] = ph[1];
        }
#pragma unroll
        for (int k = 0; k < 2; ++k) {
            genA(k, sbase + (k ? A1o : A0o), c1s[k], s1s[k], ccs[k], sss[k]);
            uint32_t wb = sbase + (k ? W1o : W0o);
            STS128(wb + swz(wroff),      wRp[2 * k]);
            STS128(wb + swz(wroff + 16), wRp[2 * k + 1]);
        }
    }

    for (int cp = 0; cp < NCP; ++cp) {
        const uint32_t st = sbase + (cp & 1) * STG;

        __syncthreads();   // pair cp visible; opposite stage free

        // ---- prefetch pair cp+1 (issued before MMA; consumed after) ----
        const int np = cp + 1;
        float c1s[2], s1s[2], ccs[2], sss[2];
        uint4 wRp[4];
        if (np < NCP) {
#pragma unroll
            for (int k = 0; k < 2; ++k) {
                int cn = 2 * np + k;
                const uint4* ph = (const uint4*)(g_Wh + ((size_t)cn * Oq + o0 + wrow) * 64 + wq * 16);
                wRp[2 * k] = ph[0]; wRp[2 * k + 1] = ph[1];
                if (cn < Iq) {
                    size_t gb = (size_t)cn * Bq + b0 + gm;
                    c1s[k] = g_c1[gb]; s1s[k] = g_s1[gb];
                    if (gh) { ccs[k] = g_c17[gb]; sss[k] = g_s17[gb]; }
                    else    { ccs[k] = c1s[k];    sss[k] = s1s[k]; }
                }
            }
        }

        // ---- MMA on pair cp (2 sub-chunks) ----
#pragma unroll
        for (int sub = 0; sub < 2; ++sub) {
            const uint32_t aB = st + (sub ? A1o : A0o);
            const uint32_t wB = st + (sub ? W1o : W0o);
#pragma unroll
            for (int kk = 0; kk < 4; ++kk) {
                uint32_t a0[4], a1[4], wh0[4], wh1[4];
                LDSM4(a0,  aB + swz(aoff + kk * 32));
                LDSM4(a1,  aB + swz(aoff + 2048 + kk * 32));
                LDSM4(wh0, wB + swz(boff + kk * 32));
                LDSM4(wh1, wB + swz(boff + 2048 + kk * 32));
#pragma unroll
                for (int mt = 0; mt < 2; ++mt) {
                    const uint32_t* A = mt ? a1 : a0;
                    HMMA(acc[mt][0], A, wh0[0], wh0[1]);
                    HMMA(acc[mt][1], A, wh0[2], wh0[3]);
                    HMMA(acc[mt][2], A, wh1[0], wh1[1]);
                    HMMA(acc[mt][3], A, wh1[2], wh1[3]);
                }
            }
        }

        // ---- generate + STS pair cp+1 into opposite stage ----
        if (np < NCP) {
            const uint32_t sn = sbase + (np & 1) * STG;
#pragma unroll
            for (int k = 0; k < 2; ++k) {
                int cn = 2 * np + k;
                genA(cn, sn + (k ? A1o : A0o), c1s[k], s1s[k], ccs[k], sss[k]);
                uint32_t wb = sn + (k ? W1o : W0o);
                STS128(wb + swz(wroff),      wRp[2 * k]);
                STS128(wb + swz(wroff + 16), wRp[2 * k + 1]);
            }
        }
    }

    // ---- epilogue ----
#pragma unroll
    for (int mt = 0; mt < 2; ++mt) {
#pragma unroll
        for (int nf = 0; nf < 4; ++nf) {
            int row = b0 + wm * 32 + mt * 16 + (lane >> 2);
            int col = o0 + wn * 32 + nf * 8 + 2 * (lane & 3);
            float bv0 = bias[col], bv1 = bias[col + 1];
            float2 v0 = make_float2(acc[mt][nf][0] + bv0, acc[mt][nf][1] + bv1);
            float2 v1 = make_float2(acc[mt][nf][2] + bv0, acc[mt][nf][3] + bv1);
            *reinterpret_cast<float2*>(out + (size_t)row * Oq + col) = v0;
            *reinterpret_cast<float2*>(out + (size_t)(row + 8) * Oq + col) = v1;
        }
    }
}

extern "C" void kernel_launch(void* const* d_in, const int* in_sizes, int n_in,
                              void* d_out, int out_size) {
    const float* x    = (const float*)d_in[0];
    const float* fc   = (const float*)d_in[1];
    const float* bias = (const float*)d_in[2];
    const float* mask = (const float*)d_in[3];
    const float* sb   = (const float*)d_in[4];
    const float* sf   = (const float*)d_in[5];
    float* out = (float*)d_out;

    cudaFuncSetAttribute(kan_gemm, cudaFuncAttributeMaxDynamicSharedMemorySize, GSMEM);

    kan_xform<<<dim3(Bq / 32, Iq / 32), 256>>>(x);
    kan_prep<<<NCH, Oq>>>(fc, mask, sb, sf);
    kan_gemm<<<dim3(Bq / 128, Oq / 64), 256, GSMEM>>>(bias, out);
}

// round 9
// speedup vs baseline: 7.0447x; 1.6053x over previous
#include <cuda_runtime.h>
#include <cuda_fp16.h>
#include <cstdint>

#define Bq 4096
#define Iq 256
#define Oq 256
#define NCH 260                 // 256 fourier chunks + 4 base chunks (K=64 each)
#define NSPLIT 4
#define CPS 65                  // chunks per split
// stage layout: A 16K | W 32K
#define AHo 0
#define WHo 16384
#define STG 49152
#define GSMEM (2*STG + 256)

// ---------- scratch (__device__ globals only) ----------
__device__ float g_c1[(size_t)Iq * Bq];
__device__ float g_s1[(size_t)Iq * Bq];
__device__ float g_c17[(size_t)Iq * Bq];
__device__ float g_s17[(size_t)Iq * Bq];
__device__ __align__(16) unsigned short g_bh[(size_t)Bq * Iq];       // silu fp16 [b][i]
__device__ __align__(16) unsigned short g_Wh[(size_t)NCH * Oq * 64]; // fp16 [chunk][j][slot]
__device__ __align__(16) float g_part[(size_t)NSPLIT * Bq * Oq];     // split-K partials

// ---------- helpers ----------
__device__ __forceinline__ uint32_t smem_u32(const void* p) {
    uint32_t a;
    asm("{ .reg .u64 t; cvta.to.shared.u64 t, %1; cvt.u32.u64 %0, t; }" : "=r"(a) : "l"(p));
    return a;
}
__device__ __forceinline__ uint32_t swz(uint32_t off) { return off ^ ((off >> 3) & 0x70); }
__device__ __forceinline__ uint32_t h2pack(float a, float b) {  // a->low half
    uint32_t r;
    asm("cvt.rn.f16x2.f32 %0, %1, %2;" : "=r"(r) : "f"(b), "f"(a));
    return r;
}
__device__ __forceinline__ void rot(float& c, float& s, float c1, float s1) {
    float t = fmaf(c, c1, -(s * s1));
    float u = fmaf(s, c1, c * s1);
    c = t; s = u;
}

#define STS128(a, v) asm volatile("st.shared.v4.b32 [%0], {%1,%2,%3,%4};" \
    :: "r"(a), "r"((v).x), "r"((v).y), "r"((v).z), "r"((v).w) : "memory")
#define LDSM4(r, addr) asm volatile( \
    "ldmatrix.sync.aligned.m8n8.x4.shared.b16 {%0,%1,%2,%3}, [%4];" \
    : "=r"((r)[0]), "=r"((r)[1]), "=r"((r)[2]), "=r"((r)[3]) : "r"(addr))
#define HMMA(d, a0v, a1v, a2v, a3v, b0v, b1v) asm volatile( \
    "mma.sync.aligned.m16n8k16.row.col.f32.f16.f16.f32 " \
    "{%0,%1,%2,%3}, {%4,%5,%6,%7}, {%8,%9}, {%0,%1,%2,%3};" \
    : "+f"((d)[0]), "+f"((d)[1]), "+f"((d)[2]), "+f"((d)[3]) \
    : "r"(a0v), "r"(a1v), "r"(a2v), "r"(a3v), "r"(b0v), "r"(b1v))
#define CPASYNC16(dst, src) asm volatile( \
    "cp.async.ca.shared.global [%0], [%1], 16;" :: "r"(dst), "l"(src))
#define CPCOMMIT() asm volatile("cp.async.commit_group;" ::: "memory")
#define CPWAIT0()  asm volatile("cp.async.wait_group 0;" ::: "memory")

// ---------- kernel 1: sincos/silu transform ----------
__global__ void kan_xform(const float* __restrict__ x) {
    __shared__ float tx[32][33];
    int b0 = blockIdx.x * 32, i0 = blockIdx.y * 32;
    int tid = threadIdx.x;
#pragma unroll
    for (int it = 0; it < 4; ++it) {
        int idx = tid + it * 256;
        int bb = idx >> 5, ii = idx & 31;
        float v = x[(size_t)(b0 + bb) * Iq + i0 + ii];
        tx[bb][ii] = v;
        float sl = v / (1.0f + expf(-v));
        __half h = __float2half_rn(sl);
        g_bh[(size_t)(b0 + bb) * Iq + i0 + ii] = *reinterpret_cast<unsigned short*>(&h);
    }
    __syncthreads();
#pragma unroll
    for (int it = 0; it < 4; ++it) {
        int idx = tid + it * 256;
        int ii = idx >> 5, bb = idx & 31;
        float v = tx[bb][ii];
        float s, c;
        sincosf(v, &s, &c);
        size_t o = (size_t)(i0 + ii) * Bq + b0 + bb;
        g_c1[o] = c; g_s1[o] = s;
        sincosf(17.0f * v, &s, &c);
        g_c17[o] = c; g_s17[o] = s;
    }
}

// ---------- kernel 2: fold weights -> fp16 ----------
__global__ void kan_prep(const float* __restrict__ fc, const float* __restrict__ mask,
                         const float* __restrict__ sb, const float* __restrict__ sf) {
    int blk = blockIdx.x, j = threadIdx.x;
    unsigned short* dh = g_Wh + ((size_t)blk * Oq + j) * 64;
    if (blk < Iq) {
        int i = blk;
        float m = mask[i * Oq + j];
        float wf = sf[i * Oq + j] * m;
        const float* f0 = fc + ((size_t)j * Iq + i) * 32;
        const float* f1 = f0 + (size_t)Oq * Iq * 32;
        for (int g = 0; g < 8; ++g) {
            uint4 vh;
            uint32_t* ph = &vh.x;
            for (int e = 0; e < 4; ++e) {
                int s0 = g * 8 + 2 * e;
                float w0 = (s0 < 32) ? wf * f0[s0] : wf * f1[s0 - 32];
                float w1 = (s0 + 1 < 32) ? wf * f0[s0 + 1] : wf * f1[s0 - 31];
                ph[e] = h2pack(w0, w1);
            }
            *reinterpret_cast<uint4*>(dh + g * 8) = vh;
        }
    } else {
        int cb = blk - Iq;
        for (int g = 0; g < 8; ++g) {
            uint4 vh;
            uint32_t* ph = &vh.x;
            for (int e = 0; e < 4; ++e) {
                int s0 = g * 8 + 2 * e;
                int ia = cb * 64 + s0, ib = ia + 1;
                float w0 = mask[ia * Oq + j] * sb[ia * Oq + j];
                float w1 = mask[ib * Oq + j] * sb[ib * Oq + j];
                ph[e] = h2pack(w0, w1);
            }
            *reinterpret_cast<uint4*>(dh + g * 8) = vh;
        }
    }
}

// ---------- kernel 3: HMMA fused GEMM, split-K, N=256 ----------
__global__ void __launch_bounds__(256, 1)
kan_gemm(float* __restrict__ dummy) {
    extern __shared__ char smem[];
    const uint32_t sbase = (smem_u32(smem) + 127) & ~127u;

    const int tid = threadIdx.x, lane = tid & 31, wid = tid >> 5;
    const int wm = wid & 3, wn = wid >> 2;          // warp grid 4m x 2n (n=128 each)
    const int b0 = blockIdx.x * 128;
    const int spl = blockIdx.y;
    const int c0 = spl * CPS;

    const int gm = tid >> 1, gh = tid & 1;          // A-gen: row, half

    float acc[2][16][4];
#pragma unroll
    for (int mt = 0; mt < 2; ++mt)
#pragma unroll
        for (int nf = 0; nf < 16; ++nf)
#pragma unroll
            for (int e = 0; e < 4; ++e) acc[mt][nf][e] = 0.0f;

    const uint32_t arow = (uint32_t)gm * 128;
    const uint32_t aoff = (uint32_t)(wm * 32 + (lane & 15)) * 128 + (lane >> 4) * 16;
    const uint32_t boff = (uint32_t)(wn * 128 + (lane & 7) + ((lane >> 4) << 3)) * 128
                        + ((lane >> 3) & 1) * 16;
    // W cp.async mapping: warp wid covers rows wid*32..wid*32+31
    const int wj = wid * 32 + (lane >> 3) ;   // + g*4 below
    const int wp = lane & 7;

    auto stageW = [&](int cn, uint32_t wB) {
        const unsigned short* src = g_Wh + (size_t)cn * Oq * 64;
#pragma unroll
        for (int g = 0; g < 8; ++g) {
            int jj = wj + g * 4;
            CPASYNC16(wB + swz((uint32_t)jj * 128 + wp * 16),
                      src + (size_t)jj * 64 + wp * 8);
        }
    };

    auto genA = [&](int cn, uint32_t aBase, float c1s, float s1s, float ccs, float sss) {
        uint32_t aH[16];
        if (cn < Iq) {
            float cc = ccs, ss = sss;
#pragma unroll
            for (int p = 0; p < 8; ++p) {
                float ca = cc, sa = ss; rot(cc, ss, c1s, s1s);
                float cb = cc, sb2 = ss; rot(cc, ss, c1s, s1s);
                aH[p]     = h2pack(ca, cb);
                aH[8 + p] = h2pack(sa, sb2);
            }
        } else {
            int cb = cn - Iq;
            const unsigned short* ph = g_bh + (size_t)(b0 + gm) * Iq + cb * 64;
            uint4 v;
            v = *(const uint4*)(ph + 16 * gh);          aH[0]=v.x; aH[1]=v.y; aH[2]=v.z; aH[3]=v.w;
            v = *(const uint4*)(ph + 16 * gh + 8);      aH[4]=v.x; aH[5]=v.y; aH[6]=v.z; aH[7]=v.w;
            v = *(const uint4*)(ph + 32 + 16 * gh);     aH[8]=v.x; aH[9]=v.y; aH[10]=v.z; aH[11]=v.w;
            v = *(const uint4*)(ph + 32 + 16 * gh + 8); aH[12]=v.x; aH[13]=v.y; aH[14]=v.z; aH[15]=v.w;
        }
        STS128(aBase + swz(arow + 32 * gh),           make_uint4(aH[0], aH[1], aH[2], aH[3]));
        STS128(aBase + swz(arow + 32 * gh + 16),      make_uint4(aH[4], aH[5], aH[6], aH[7]));
        STS128(aBase + swz(arow + 64 + 32 * gh),      make_uint4(aH[8], aH[9], aH[10], aH[11]));
        STS128(aBase + swz(arow + 64 + 32 * gh + 16), make_uint4(aH[12], aH[13], aH[14], aH[15]));
    };

    // ---- prologue: chunk c0 into stage 0 ----
    {
        stageW(c0, sbase + WHo);
        CPCOMMIT();
        float c1s = 0.f, s1s = 0.f, ccs = 0.f, sss = 0.f;
        if (c0 < Iq) {
            size_t gb = (size_t)c0 * Bq + b0 + gm;
            c1s = g_c1[gb]; s1s = g_s1[gb];
            if (gh) { ccs = g_c17[gb]; sss = g_s17[gb]; }
            else    { ccs = c1s;       sss = s1s; }
        }
        genA(c0, sbase + AHo, c1s, s1s, ccs, sss);
        CPWAIT0();
    }

    for (int ci = 0; ci < CPS; ++ci) {
        const int c = c0 + ci;
        const uint32_t st = sbase + (ci & 1) * STG;

        __syncthreads();   // stage (ci&1) ready; opposite stage free

        const int cn = c + 1;
        const bool more = (ci + 1 < CPS);
        float c1s = 0.f, s1s = 0.f, ccs = 0.f, sss = 0.f;
        if (more) {
            const uint32_t sn = sbase + ((ci + 1) & 1) * STG;
            stageW(cn, sn + WHo);            // async, no regs held
            CPCOMMIT();
            if (cn < Iq) {
                size_t gb = (size_t)cn * Bq + b0 + gm;
                c1s = g_c1[gb]; s1s = g_s1[gb];
                if (gh) { ccs = g_c17[gb]; sss = g_s17[gb]; }
                else    { ccs = c1s;       sss = s1s; }
            }
        }

        // ---- MMA on chunk c ----
        const uint32_t aB = st + AHo, wB = st + WHo;
#pragma unroll
        for (int kk = 0; kk < 4; ++kk) {
            uint32_t a0[4], a1[4];
            LDSM4(a0, aB + swz(aoff + kk * 32));
            LDSM4(a1, aB + swz(aoff + 2048 + kk * 32));
#pragma unroll
            for (int ng = 0; ng < 8; ++ng) {
                uint32_t w[4];
                LDSM4(w, wB + swz(boff + (uint32_t)ng * 2048 + kk * 32));
                HMMA(acc[0][2 * ng],     a0[0], a0[1], a0[2], a0[3], w[0], w[1]);
                HMMA(acc[0][2 * ng + 1], a0[0], a0[1], a0[2], a0[3], w[2], w[3]);
                HMMA(acc[1][2 * ng],     a1[0], a1[1], a1[2], a1[3], w[0], w[1]);
                HMMA(acc[1][2 * ng + 1], a1[0], a1[1], a1[2], a1[3], w[2], w[3]);
            }
        }

        // ---- generate + STS A(c+1) into opposite stage ----
        if (more) {
            genA(cn, sbase + ((ci + 1) & 1) * STG + AHo, c1s, s1s, ccs, sss);
        }
        CPWAIT0();
    }

    // ---- epilogue: write fp32 partials ----
    float* pp = g_part + (size_t)spl * Bq * Oq;
#pragma unroll
    for (int mt = 0; mt < 2; ++mt) {
#pragma unroll
        for (int nf = 0; nf < 16; ++nf) {
            int row = b0 + wm * 32 + mt * 16 + (lane >> 2);
            int col = wn * 128 + nf * 8 + 2 * (lane & 3);
            *reinterpret_cast<float2*>(pp + (size_t)row * Oq + col) =
                make_float2(acc[mt][nf][0], acc[mt][nf][1]);
            *reinterpret_cast<float2*>(pp + (size_t)(row + 8) * Oq + col) =
                make_float2(acc[mt][nf][2], acc[mt][nf][3]);
        }
    }
}

// ---------- kernel 4: split-K reduce + bias ----------
__global__ void kan_reduce(const float* __restrict__ bias, float* __restrict__ out) {
    int idx = blockIdx.x * 256 + threadIdx.x;           // float4 index
    const float4* p0 = (const float4*)g_part;
    const size_t n4 = (size_t)Bq * Oq / 4;
    float4 a = p0[idx];
    float4 b = p0[n4 + idx];
    float4 c = p0[2 * n4 + idx];
    float4 d = p0[3 * n4 + idx];
    float4 bv = ((const float4*)bias)[idx & 63];
    float4 r;
    r.x = a.x + b.x + c.x + d.x + bv.x;
    r.y = a.y + b.y + c.y + d.y + bv.y;
    r.z = a.z + b.z + c.z + d.z + bv.z;
    r.w = a.w + b.w + c.w + d.w + bv.w;
    ((float4*)out)[idx] = r;
}

extern "C" void kernel_launch(void* const* d_in, const int* in_sizes, int n_in,
                              void* d_out, int out_size) {
    const float* x    = (const float*)d_in[0];
    const float* fc   = (const float*)d_in[1];
    const float* bias = (const float*)d_in[2];
    const float* mask = (const float*)d_in[3];
    const float* sb   = (const float*)d_in[4];
    const float* sf   = (const float*)d_in[5];
    float* out = (float*)d_out;

    cudaFuncSetAttribute(kan_gemm, cudaFuncAttributeMaxDynamicSharedMemorySize, GSMEM);

    kan_xform<<<dim3(Bq / 32, Iq / 32), 256>>>(x);
    kan_prep<<<NCH, Oq>>>(fc, mask, sb, sf);
    kan_gemm<<<dim3(Bq / 128, NSPLIT), 256, GSMEM>>>(out);
    kan_reduce<<<Bq * Oq / 4 / 256, 256>>>(bias, out);
}